// round 7
// baseline (speedup 1.0000x reference)
#include <cuda_runtime.h>
#include <cuda_bf16.h>
#include <cstdint>

#define NM 20000
#define ND 8000
#define NE 200000
#define FIN 384
#define HD 512
#define H1 512
#define OD 256

typedef __nv_bfloat16 bf16;
typedef __nv_bfloat162 bf162;

// ---------------- scratch (device globals) ----------------
__device__ bf16 g_mfh[NM*FIN], g_mfl[NM*FIN];
__device__ bf16 g_dfh[ND*FIN], g_dfl[ND*FIN];
__device__ bf16 g_xmh[NM*HD],  g_xml[NM*HD];
__device__ bf16 g_xdh[ND*HD],  g_xdl[ND*HD];
__device__ bf16 g_adh[ND*HD],  g_adl[ND*HD];
__device__ bf16 g_hmh[NM*H1],  g_hml[NM*H1];
__device__ bf16 g_hdh[ND*H1],  g_hdl[ND*H1];
__device__ float g_qd[ND*H1];
__device__ float g_base[NM*H1];
__device__ float g_ud[ND*OD];
__device__ bf16 g_wmh[FIN*HD], g_wml[FIN*HD];
__device__ bf16 g_wdh[FIN*HD], g_wdl[FIN*HD];
__device__ bf16 g_w1mdlh[HD*H1], g_w1mdll[HD*H1];
__device__ bf16 g_w1mdrh[HD*H1], g_w1mdrl[HD*H1];
__device__ bf16 g_w1dmlh[HD*H1], g_w1dmll[HD*H1];
__device__ bf16 g_w1dmrh[HD*H1], g_w1dmrl[HD*H1];
__device__ bf16 g_w2mdlh[H1*OD], g_w2mdll[H1*OD];
__device__ bf16 g_w2mdrh[H1*OD], g_w2mdrl[H1*OD];
__device__ bf16 g_w2dmlh[H1*OD], g_w2dmll[H1*OD];
__device__ bf16 g_w2dmrh[H1*OD], g_w2dmrl[H1*OD];
__device__ int g_cnt_m[NM], g_cnt_d[ND];
__device__ int g_off_m[NM+1], g_off_d[ND+1];
__device__ int g_cur_m[NM], g_cur_d[ND];
__device__ int g_csr_src[NE];
__device__ int g_csr_dst[NE];

// ---------------- PTX helpers ----------------
__device__ __forceinline__ void ldsm_x4(uint32_t& r0,uint32_t& r1,uint32_t& r2,uint32_t& r3,uint32_t a){
    asm volatile("ldmatrix.sync.aligned.m8n8.x4.shared.b16 {%0,%1,%2,%3},[%4];"
                 :"=r"(r0),"=r"(r1),"=r"(r2),"=r"(r3):"r"(a));
}
__device__ __forceinline__ void ldsm_x4t(uint32_t& r0,uint32_t& r1,uint32_t& r2,uint32_t& r3,uint32_t a){
    asm volatile("ldmatrix.sync.aligned.m8n8.x4.trans.shared.b16 {%0,%1,%2,%3},[%4];"
                 :"=r"(r0),"=r"(r1),"=r"(r2),"=r"(r3):"r"(a));
}
__device__ __forceinline__ void mma_bf16(float* c, const uint32_t* a, uint32_t b0, uint32_t b1){
    asm volatile("mma.sync.aligned.m16n8k16.row.col.f32.bf16.bf16.f32 "
        "{%0,%1,%2,%3},{%4,%5,%6,%7},{%8,%9},{%0,%1,%2,%3};"
        :"+f"(c[0]),"+f"(c[1]),"+f"(c[2]),"+f"(c[3])
        :"r"(a[0]),"r"(a[1]),"r"(a[2]),"r"(a[3]),"r"(b0),"r"(b1));
}
__device__ __forceinline__ void cpa16(uint32_t d, const void* s, bool p){
    int sz = p ? 16 : 0;
    asm volatile("cp.async.cg.shared.global [%0],[%1],16,%2;"::"r"(d),"l"(s),"r"(sz));
}

// smem geometry (bf16 elements) — R2 proven
#define SA 40
#define SB 136
#define ASZ (128*SA)
#define BSZ (32*SB)
#define STAGE_E (2*ASZ + 2*BSZ)
#define GEMM_SMEM_BYTES (2*STAGE_E*2)

// flags
#define F_BIAS  1
#define F_RELU  2
#define F_GATH  4
#define F_SPLIT 8

struct GemmDesc {
    const bf16 *A1h,*A1l,*B1h,*B1l;
    const bf16 *A2h,*A2l,*B2h,*B2l;
    int K1, K2, M, N;
    const float *bias, *Demb; const int* idx;
    float* C; bf16 *Ch, *Cl;
    int flags;
    int start, tx;
};
// gather kinds: 1 = split-mean (bf16 hi/lo in -> split out)
//               2 = relu-mean  (f32 Q mean + f32 Base, relu -> split out)
//               3 = acc-mean   (f32 Q mean accumulated into f32 C)
struct GatherDesc {
    int kind, width, nrows;
    const bf16 *Xh, *Xl;
    const float *Q, *Base;
    const int *off, *nbr;
    bf16 *Ch, *Cl;
    float *C;
};
struct Batch {
    GemmDesc g[3]; int ng; int gemm_total;
    GatherDesc t; int nt;
};

__device__ __forceinline__ void split_store(bf162* oh, bf162* ol,
                                            float x0, float x1, float x2, float x3)
{
    bf16 h0=__float2bfloat16(x0), h1=__float2bfloat16(x1);
    bf16 h2=__float2bfloat16(x2), h3=__float2bfloat16(x3);
    bf16 l0=__float2bfloat16(x0-__bfloat162float(h0));
    bf16 l1=__float2bfloat16(x1-__bfloat162float(h1));
    bf16 l2=__float2bfloat16(x2-__bfloat162float(h2));
    bf16 l3=__float2bfloat16(x3-__bfloat162float(h3));
    oh[0] = __halves2bfloat162(h0,h1); oh[1] = __halves2bfloat162(h2,h3);
    ol[0] = __halves2bfloat162(l0,l1); ol[1] = __halves2bfloat162(l2,l3);
}

// ---------------- fused GEMM + gather mega-kernel ----------------
__global__ __launch_bounds__(256,2) void mega_kernel(Batch b)
{
    extern __shared__ bf16 smem[];
    const int tid  = threadIdx.x;

    if ((int)blockIdx.x >= b.gemm_total){
        // ---------- gather path ----------
        const GatherDesc t = b.t;
        const int tpr = t.width >> 2;          // threads per row
        const int rpb = 256 / tpr;             // rows per block
        int rel  = blockIdx.x - b.gemm_total;
        int row  = rel * rpb + tid / tpr;
        if (row >= t.nrows) return;
        int lane = tid & (tpr - 1);
        int s = t.off[row], e = t.off[row + 1];
        float a0=0.f,a1=0.f,a2=0.f,a3=0.f;
        if (t.kind == 1){
#pragma unroll 2
            for (int i = s; i < e; i++){
                int nb = __ldg(&t.nbr[i]);
                const bf162* ph = (const bf162*)(t.Xh + (size_t)nb*t.width);
                const bf162* pl = (const bf162*)(t.Xl + (size_t)nb*t.width);
                bf162 h0 = __ldg(&ph[2*lane]), h1 = __ldg(&ph[2*lane+1]);
                bf162 l0 = __ldg(&pl[2*lane]), l1 = __ldg(&pl[2*lane+1]);
                a0 += __bfloat162float(h0.x) + __bfloat162float(l0.x);
                a1 += __bfloat162float(h0.y) + __bfloat162float(l0.y);
                a2 += __bfloat162float(h1.x) + __bfloat162float(l1.x);
                a3 += __bfloat162float(h1.y) + __bfloat162float(l1.y);
            }
            float inv = (e > s) ? 1.0f/(float)(e - s) : 0.0f;
            a0 *= inv; a1 *= inv; a2 *= inv; a3 *= inv;
            split_store((bf162*)(t.Ch + (size_t)row*t.width) + 2*lane,
                        (bf162*)(t.Cl + (size_t)row*t.width) + 2*lane, a0,a1,a2,a3);
        } else if (t.kind == 2){
#pragma unroll 2
            for (int i = s; i < e; i++){
                int nb = __ldg(&t.nbr[i]);
                float4 v = __ldg((const float4*)(t.Q + (size_t)nb*t.width) + lane);
                a0 += v.x; a1 += v.y; a2 += v.z; a3 += v.w;
            }
            float inv = (e > s) ? 1.0f/(float)(e - s) : 0.0f;
            float4 bb = __ldg((const float4*)(t.Base + (size_t)row*t.width) + lane);
            a0 = fmaxf(bb.x + a0*inv, 0.f);
            a1 = fmaxf(bb.y + a1*inv, 0.f);
            a2 = fmaxf(bb.z + a2*inv, 0.f);
            a3 = fmaxf(bb.w + a3*inv, 0.f);
            split_store((bf162*)(t.Ch + (size_t)row*t.width) + 2*lane,
                        (bf162*)(t.Cl + (size_t)row*t.width) + 2*lane, a0,a1,a2,a3);
        } else {
#pragma unroll 2
            for (int i = s; i < e; i++){
                int nb = __ldg(&t.nbr[i]);
                float4 v = __ldg((const float4*)(t.Q + (size_t)nb*t.width) + lane);
                a0 += v.x; a1 += v.y; a2 += v.z; a3 += v.w;
            }
            float inv = (e > s) ? 1.0f/(float)(e - s) : 0.0f;
            float4* cp = (float4*)(t.C + (size_t)row*t.width) + lane;
            float4 o = *cp;
            o.x += a0*inv; o.y += a1*inv; o.z += a2*inv; o.w += a3*inv;
            *cp = o;
        }
        return;
    }

    // ---------- GEMM path (R2-proven core) ----------
    uint32_t sbase = (uint32_t)__cvta_generic_to_shared(smem);
    const int lane = tid & 31;
    const int wid  = tid >> 5;
    const int wm   = (wid & 3) * 32;
    const int wn   = (wid >> 2) * 64;

    int gi = 0;
    if (b.ng > 1 && (int)blockIdx.x >= b.g[1].start) gi = 1;
    if (b.ng > 2 && (int)blockIdx.x >= b.g[2].start) gi = 2;
    const GemmDesc d = b.g[gi];

    const int rel = blockIdx.x - d.start;
    const int bn  = (rel % d.tx) * 128;
    const int bm  = (rel / d.tx) * 128;
    const int M = d.M, N = d.N;
    const int S1 = d.K1 >> 5, S2 = d.K2 >> 5, S = S1 + S2;

    float acc[2][8][4];
#pragma unroll
    for (int i=0;i<2;i++)
#pragma unroll
        for (int j=0;j<8;j++)
#pragma unroll
            for (int k=0;k<4;k++) acc[i][j][k] = 0.f;

    auto prefetch = [&](int s){
        const bf16 *Ah,*Al,*Bh,*Bl; int K,k0;
        if (s < S1){ Ah=d.A1h; Al=d.A1l; Bh=d.B1h; Bl=d.B1l; K=d.K1; k0=s<<5; }
        else       { Ah=d.A2h; Al=d.A2l; Bh=d.B2h; Bl=d.B2l; K=d.K2; k0=(s-S1)<<5; }
        uint32_t sb = sbase + (uint32_t)((s&1)*STAGE_E*2);
        int ar = tid>>2, ac = (tid&3)*8;
#pragma unroll
        for (int i=0;i<2;i++){
            int row = bm + ar + 64*i;
            bool ok = row < M;
            int sr = ok ? row : 0;
            uint32_t dd = sb + (uint32_t)(((ar+64*i)*SA + ac)*2);
            cpa16(dd,          Ah + (size_t)sr*K + k0 + ac, ok);
            cpa16(dd + ASZ*2,  Al + (size_t)sr*K + k0 + ac, ok);
        }
        int bk = tid>>4, bc = (tid&15)*8;
#pragma unroll
        for (int i=0;i<2;i++){
            int k = bk + 16*i;
            uint32_t dd = sb + (uint32_t)(((2*ASZ) + k*SB + bc)*2);
            size_t go = (size_t)(k0 + k)*N + bn + bc;
            cpa16(dd,          Bh + go, true);
            cpa16(dd + BSZ*2,  Bl + go, true);
        }
        asm volatile("cp.async.commit_group;");
    };

    prefetch(0);
    for (int s=0;s<S;s++){
        if (s+1 < S){
            prefetch(s+1);
            asm volatile("cp.async.wait_group 1;");
        } else {
            asm volatile("cp.async.wait_group 0;");
        }
        __syncthreads();
        uint32_t sb = sbase + (uint32_t)((s&1)*STAGE_E*2);
#pragma unroll
        for (int kk=0;kk<2;kk++){
            const int k16 = kk*16;
            const int loff = (lane>>1)&8;
            uint32_t ah[2][4], al[2][4];
#pragma unroll
            for (int mf=0;mf<2;mf++){
                uint32_t a = sb + (uint32_t)((((wm + mf*16 + (lane&15))*SA) + k16 + loff)*2);
                ldsm_x4(ah[mf][0],ah[mf][1],ah[mf][2],ah[mf][3], a);
                ldsm_x4(al[mf][0],al[mf][1],al[mf][2],al[mf][3], a + ASZ*2);
            }
#pragma unroll
            for (int nb=0;nb<4;nb++){
                uint32_t a = sb + (uint32_t)(((2*ASZ) + (k16 + (lane&15))*SB + wn + nb*16 + loff)*2);
                uint32_t bh[4], bl[4];
                ldsm_x4t(bh[0],bh[1],bh[2],bh[3], a);
                ldsm_x4t(bl[0],bl[1],bl[2],bl[3], a + BSZ*2);
#pragma unroll
                for (int h=0;h<2;h++){
#pragma unroll
                    for (int mf=0;mf<2;mf++){
                        float* c = acc[mf][nb*2+h];
                        mma_bf16(c, ah[mf], bh[2*h], bh[2*h+1]);
                        mma_bf16(c, ah[mf], bl[2*h], bl[2*h+1]);
                        mma_bf16(c, al[mf], bh[2*h], bh[2*h+1]);
                    }
                }
            }
        }
        __syncthreads();
    }

    const int fl = d.flags;
#pragma unroll
    for (int mf=0;mf<2;mf++){
#pragma unroll
        for (int nf=0;nf<8;nf++){
            int col = bn + wn + nf*8 + (lane&3)*2;
#pragma unroll
            for (int half=0;half<2;half++){
                int row = bm + wm + mf*16 + (lane>>2) + half*8;
                if (row >= M) continue;
                float v0 = acc[mf][nf][half*2+0];
                float v1 = acc[mf][nf][half*2+1];
                if (fl & F_BIAS){ v0 += __ldg(&d.bias[col]); v1 += __ldg(&d.bias[col+1]); }
                if (fl & F_GATH){
                    int g = __ldg(&d.idx[row]);
                    const float* e = d.Demb + (size_t)g*N + col;
                    v0 += __ldg(&e[0]); v1 += __ldg(&e[1]);
                }
                if (fl & F_RELU){ v0 = fmaxf(v0,0.f); v1 = fmaxf(v1,0.f); }
                if (fl & F_SPLIT){
                    bf16 h0=__float2bfloat16(v0), h1=__float2bfloat16(v1);
                    bf16 l0=__float2bfloat16(v0-__bfloat162float(h0));
                    bf16 l1=__float2bfloat16(v1-__bfloat162float(h1));
                    *(bf162*)(d.Ch + (size_t)row*N + col) = __halves2bfloat162(h0,h1);
                    *(bf162*)(d.Cl + (size_t)row*N + col) = __halves2bfloat162(l0,l1);
                } else {
                    float2 o; o.x=v0; o.y=v1;
                    *(float2*)(d.C + (size_t)row*N + col) = o;
                }
            }
        }
    }
}

// ---------------- batched split fp32 -> (bf16 hi, bf16 lo) ----------------
struct SplitSet { const float* x[4]; bf16* h[4]; bf16* l[4]; int n4[4]; };
__global__ void bsplit_kernel(SplitSet ss)
{
    int z = blockIdx.y;
    const float* X = ss.x[z]; bf16* H = ss.h[z]; bf16* L = ss.l[z];
    int n4 = ss.n4[z];
    int i = blockIdx.x*blockDim.x + threadIdx.x;
    if (i < n4){
        float4 v = ((const float4*)X)[i];
        bf16 h0=__float2bfloat16(v.x), h1=__float2bfloat16(v.y);
        bf16 h2=__float2bfloat16(v.z), h3=__float2bfloat16(v.w);
        bf16 l0=__float2bfloat16(v.x-__bfloat162float(h0));
        bf16 l1=__float2bfloat16(v.y-__bfloat162float(h1));
        bf16 l2=__float2bfloat16(v.z-__bfloat162float(h2));
        bf16 l3=__float2bfloat16(v.w-__bfloat162float(h3));
        ((bf162*)H)[2*i]   = __halves2bfloat162(h0,h1);
        ((bf162*)H)[2*i+1] = __halves2bfloat162(h2,h3);
        ((bf162*)L)[2*i]   = __halves2bfloat162(l0,l1);
        ((bf162*)L)[2*i+1] = __halves2bfloat162(l2,l3);
    }
}

// ---------------- CSR build ----------------
__global__ void zero_kernel(int* a, int na, int* b, int nb)
{
    int i = blockIdx.x*blockDim.x + threadIdx.x;
    if (i < na) a[i] = 0;
    if (i < nb) b[i] = 0;
}

__global__ void count_edges_kernel(const int* __restrict__ src, const int* __restrict__ dst,
                                   int* __restrict__ cm, int* __restrict__ cd, int E)
{
    int i = blockIdx.x * blockDim.x + threadIdx.x;
    if (i < E) {
        atomicAdd(&cd[dst[i]], 1);
        atomicAdd(&cm[src[i]], 1);
    }
}

__global__ void exscan2_kernel(const int* __restrict__ cnt_d, int* __restrict__ off_d, int* __restrict__ cur_d, int n_d,
                               const int* __restrict__ cnt_m, int* __restrict__ off_m, int* __restrict__ cur_m, int n_m)
{
    const int* cnt; int* off; int* cur; int n;
    if (blockIdx.x == 0){ cnt = cnt_d; off = off_d; cur = cur_d; n = n_d; }
    else               { cnt = cnt_m; off = off_m; cur = cur_m; n = n_m; }
    __shared__ int wsum[32];
    int t = threadIdx.x;
    int chunk = (n + 1023) >> 10;
    int s = t * chunk; if (s > n) s = n;
    int e = s + chunk; if (e > n) e = n;
    int sum = 0;
    for (int i = s; i < e; i++) sum += cnt[i];
    int lane = t & 31, w = t >> 5;
    int v = sum;
#pragma unroll
    for (int dd = 1; dd < 32; dd <<= 1){
        int o = __shfl_up_sync(0xFFFFFFFFu, v, dd);
        if (lane >= dd) v += o;
    }
    if (lane == 31) wsum[w] = v;
    __syncthreads();
    if (w == 0){
        int x = wsum[lane];
#pragma unroll
        for (int dd = 1; dd < 32; dd <<= 1){
            int o = __shfl_up_sync(0xFFFFFFFFu, x, dd);
            if (lane >= dd) x += o;
        }
        wsum[lane] = x;
    }
    __syncthreads();
    int run = v - sum + (w > 0 ? wsum[w-1] : 0);
    for (int i = s; i < e; i++){
        off[i] = run; cur[i] = run; run += cnt[i];
    }
    if (t == 1023) off[n] = run;
}

__global__ void fill_csr_kernel(const int* __restrict__ src, const int* __restrict__ dst,
                                int* __restrict__ cur_m, int* __restrict__ cur_d,
                                int* __restrict__ csr_src, int* __restrict__ csr_dst, int E)
{
    int i = blockIdx.x * blockDim.x + threadIdx.x;
    if (i < E) {
        int m = src[i], d = dst[i];
        int p = atomicAdd(&cur_d[d], 1);
        csr_src[p] = m;
        int q = atomicAdd(&cur_m[m], 1);
        csr_dst[q] = d;
    }
}

// ---------------- host orchestration ----------------
#define SYM(p, s) cudaGetSymbolAddress((void**)&(p), s)

static inline GemmDesc mk_desc(
    const bf16* A1h, const bf16* A1l, const bf16* B1h, const bf16* B1l, int K1,
    const bf16* A2h, const bf16* A2l, const bf16* B2h, const bf16* B2l, int K2,
    int M, int N, const float* bias, const float* Demb, const int* idx,
    float* C, bf16* Ch, bf16* Cl, int flags)
{
    GemmDesc d;
    d.A1h=A1h; d.A1l=A1l; d.B1h=B1h; d.B1l=B1l; d.K1=K1;
    d.A2h=A2h; d.A2l=A2l; d.B2h=B2h; d.B2l=B2l; d.K2=K2;
    d.M=M; d.N=N; d.bias=bias; d.Demb=Demb; d.idx=idx;
    d.C=C; d.Ch=Ch; d.Cl=Cl; d.flags=flags;
    d.start=0; d.tx=N/128;
    return d;
}

static inline void launch_mixed(GemmDesc* descs, int n, const GatherDesc* gt)
{
    Batch b;
    int total = 0;
    for (int i = 0; i < n; i++){
        descs[i].start = total;
        total += descs[i].tx * ((descs[i].M + 127)/128);
        b.g[i] = descs[i];
    }
    for (int i = n; i < 3; i++){ b.g[i] = descs[n-1]; b.g[i].start = 0x7FFFFFFF; }
    b.ng = n;
    b.gemm_total = total;
    int gblocks = 0;
    if (gt){
        b.t = *gt; b.nt = 1;
        int tpr = gt->width >> 2;
        int rpb = 256 / tpr;
        gblocks = (gt->nrows + rpb - 1) / rpb;
    } else {
        GatherDesc z = {}; b.t = z; b.nt = 0;
    }
    mega_kernel<<<total + gblocks, 256, GEMM_SMEM_BYTES>>>(b);
}

extern "C" void kernel_launch(void* const* d_in, const int* in_sizes, int n_in,
                              void* d_out, int out_size)
{
    const float* mf   = (const float*)d_in[0];
    const float* df   = (const float*)d_in[1];
    const int*   mid  = (const int*)d_in[2];
    const int*   did  = (const int*)d_in[3];
    const int*   esrc = (const int*)d_in[4];
    const int*   edst = (const int*)d_in[5];
    const float* Wm   = (const float*)d_in[6];
    const float* bm   = (const float*)d_in[7];
    const float* Wd   = (const float*)d_in[8];
    const float* bd   = (const float*)d_in[9];
    const float* memb = (const float*)d_in[10];
    const float* demb = (const float*)d_in[11];
    const float* W1mdl = (const float*)d_in[12];
    const float* b1md  = (const float*)d_in[13];
    const float* W1mdr = (const float*)d_in[14];
    const float* W1dml = (const float*)d_in[15];
    const float* b1dm  = (const float*)d_in[16];
    const float* W1dmr = (const float*)d_in[17];
    const float* W2mdl = (const float*)d_in[18];
    const float* b2md  = (const float*)d_in[19];
    const float* W2mdr = (const float*)d_in[20];
    const float* W2dml = (const float*)d_in[21];
    const float* b2dm  = (const float*)d_in[22];
    const float* W2dmr = (const float*)d_in[23];

    float* out = (float*)d_out;
    float* o_m = out;
    float* o_d = out + (size_t)NM * OD;

    bf16 *mfh,*mfl,*dfh,*dfl,*xmh,*xml,*xdh,*xdl,*adh,*adl,*hmh,*hml,*hdh,*hdl;
    bf16 *wmh,*wml,*wdh,*wdl;
    bf16 *w1mdlh,*w1mdll,*w1mdrh,*w1mdrl,*w1dmlh,*w1dmll,*w1dmrh,*w1dmrl;
    bf16 *w2mdlh,*w2mdll,*w2mdrh,*w2mdrl,*w2dmlh,*w2dmll,*w2dmrh,*w2dmrl;
    float *qd,*basem,*ud;
    int *cnt_m,*cnt_d,*off_m,*off_d,*cur_m,*cur_d,*csr_src,*csr_dst;
    SYM(mfh,g_mfh); SYM(mfl,g_mfl); SYM(dfh,g_dfh); SYM(dfl,g_dfl);
    SYM(xmh,g_xmh); SYM(xml,g_xml); SYM(xdh,g_xdh); SYM(xdl,g_xdl);
    SYM(adh,g_adh); SYM(adl,g_adl);
    SYM(hmh,g_hmh); SYM(hml,g_hml); SYM(hdh,g_hdh); SYM(hdl,g_hdl);
    SYM(wmh,g_wmh); SYM(wml,g_wml); SYM(wdh,g_wdh); SYM(wdl,g_wdl);
    SYM(w1mdlh,g_w1mdlh); SYM(w1mdll,g_w1mdll); SYM(w1mdrh,g_w1mdrh); SYM(w1mdrl,g_w1mdrl);
    SYM(w1dmlh,g_w1dmlh); SYM(w1dmll,g_w1dmll); SYM(w1dmrh,g_w1dmrh); SYM(w1dmrl,g_w1dmrl);
    SYM(w2mdlh,g_w2mdlh); SYM(w2mdll,g_w2mdll); SYM(w2mdrh,g_w2mdrh); SYM(w2mdrl,g_w2mdrl);
    SYM(w2dmlh,g_w2dmlh); SYM(w2dmll,g_w2dmll); SYM(w2dmrh,g_w2dmrh); SYM(w2dmrl,g_w2dmrl);
    SYM(qd,g_qd); SYM(basem,g_base); SYM(ud,g_ud);
    SYM(cnt_m,g_cnt_m); SYM(cnt_d,g_cnt_d); SYM(off_m,g_off_m); SYM(off_d,g_off_d);
    SYM(cur_m,g_cur_m); SYM(cur_d,g_cur_d); SYM(csr_src,g_csr_src); SYM(csr_dst,g_csr_dst);

    cudaFuncSetAttribute(mega_kernel, cudaFuncAttributeMaxDynamicSharedMemorySize, GEMM_SMEM_BYTES);

    // 0) CSR build
    zero_kernel<<<(NM + 255)/256, 256>>>(cnt_m, NM, cnt_d, ND);
    count_edges_kernel<<<(NE + 255) / 256, 256>>>(esrc, edst, cnt_m, cnt_d, NE);
    exscan2_kernel<<<2, 1024>>>(cnt_d, off_d, cur_d, ND, cnt_m, off_m, cur_m, NM);
    fill_csr_kernel<<<(NE + 255) / 256, 256>>>(esrc, edst, cur_m, cur_d, csr_src, csr_dst, NE);

    // 1) splits
    {
        SplitSet s1;
        s1.x[0]=mf; s1.h[0]=mfh; s1.l[0]=mfl; s1.n4[0]=NM*FIN/4;
        s1.x[1]=df; s1.h[1]=dfh; s1.l[1]=dfl; s1.n4[1]=ND*FIN/4;
        s1.x[2]=Wm; s1.h[2]=wmh; s1.l[2]=wml; s1.n4[2]=FIN*HD/4;
        s1.x[3]=Wd; s1.h[3]=wdh; s1.l[3]=wdl; s1.n4[3]=FIN*HD/4;
        int mx = NM*FIN/4;
        bsplit_kernel<<<dim3((mx + 255)/256, 4), 256>>>(s1);

        SplitSet s2;
        s2.x[0]=W1mdl; s2.h[0]=w1mdlh; s2.l[0]=w1mdll; s2.n4[0]=HD*H1/4;
        s2.x[1]=W1mdr; s2.h[1]=w1mdrh; s2.l[1]=w1mdrl; s2.n4[1]=HD*H1/4;
        s2.x[2]=W1dml; s2.h[2]=w1dmlh; s2.l[2]=w1dmll; s2.n4[2]=HD*H1/4;
        s2.x[3]=W1dmr; s2.h[3]=w1dmrh; s2.l[3]=w1dmrl; s2.n4[3]=HD*H1/4;
        bsplit_kernel<<<dim3((HD*H1/4 + 255)/256, 4), 256>>>(s2);

        SplitSet s3;
        s3.x[0]=W2mdl; s3.h[0]=w2mdlh; s3.l[0]=w2mdll; s3.n4[0]=H1*OD/4;
        s3.x[1]=W2mdr; s3.h[1]=w2mdrh; s3.l[1]=w2mdrl; s3.n4[1]=H1*OD/4;
        s3.x[2]=W2dml; s3.h[2]=w2dmlh; s3.l[2]=w2dmll; s3.n4[2]=H1*OD/4;
        s3.x[3]=W2dmr; s3.h[3]=w2dmrh; s3.l[3]=w2dmrl; s3.n4[3]=H1*OD/4;
        bsplit_kernel<<<dim3((H1*OD/4 + 255)/256, 4), 256>>>(s3);
    }

    // L1: both encoders
    {
        GemmDesc ds[2] = {
            mk_desc(mfh, mfl, wmh, wml, FIN, 0,0,0,0, 0,
                    NM, HD, bm, memb, mid, nullptr, xmh, xml, F_BIAS|F_GATH|F_SPLIT),
            mk_desc(dfh, dfl, wdh, wdl, FIN, 0,0,0,0, 0,
                    ND, HD, bd, demb, did, nullptr, xdh, xdl, F_BIAS|F_GATH|F_SPLIT)
        };
        launch_mixed(ds, 2, nullptr);
    }

    // L2: qd + base_m GEMMs  ||  gather x_m -> agg_d
    {
        GemmDesc ds[2] = {
            mk_desc(xdh, xdl, w1dmlh, w1dmll, HD, 0,0,0,0, 0,
                    ND, H1, nullptr, nullptr, nullptr, qd, nullptr, nullptr, 0),
            mk_desc(xmh, xml, w1dmrh, w1dmrl, HD, 0,0,0,0, 0,
                    NM, H1, b1dm, nullptr, nullptr, basem, nullptr, nullptr, F_BIAS)
        };
        GatherDesc t; t.kind=1; t.width=HD; t.nrows=ND;
        t.Xh=xmh; t.Xl=xml; t.Q=nullptr; t.Base=nullptr;
        t.off=off_d; t.nbr=csr_src; t.Ch=adh; t.Cl=adl; t.C=nullptr;
        launch_mixed(ds, 2, &t);
    }

    // L3: L1md dual-K GEMM -> h_d  ||  relu-gather -> h_m
    {
        GemmDesc ds[1] = {
            mk_desc(adh, adl, w1mdlh, w1mdll, HD, xdh, xdl, w1mdrh, w1mdrl, HD,
                    ND, H1, b1md, nullptr, nullptr, nullptr, hdh, hdl, F_BIAS|F_RELU|F_SPLIT)
        };
        GatherDesc t; t.kind=2; t.width=H1; t.nrows=NM;
        t.Xh=nullptr; t.Xl=nullptr; t.Q=qd; t.Base=basem;
        t.off=off_m; t.nbr=csr_dst; t.Ch=hmh; t.Cl=hml; t.C=nullptr;
        launch_mixed(ds, 1, &t);
    }

    // L4: ud + o_m GEMMs  ||  gather h_m -> agg_d
    {
        GemmDesc ds[2] = {
            mk_desc(hdh, hdl, w2dmlh, w2dmll, H1, 0,0,0,0, 0,
                    ND, OD, nullptr, nullptr, nullptr, ud, nullptr, nullptr, 0),
            mk_desc(hmh, hml, w2dmrh, w2dmrl, H1, 0,0,0,0, 0,
                    NM, OD, b2dm, nullptr, nullptr, o_m, nullptr, nullptr, F_BIAS)
        };
        GatherDesc t; t.kind=1; t.width=H1; t.nrows=ND;
        t.Xh=hmh; t.Xl=hml; t.Q=nullptr; t.Base=nullptr;
        t.off=off_d; t.nbr=csr_src; t.Ch=adh; t.Cl=adl; t.C=nullptr;
        launch_mixed(ds, 2, &t);
    }

    // L5: L2md dual-K GEMM -> o_d  ||  acc-gather ud -> o_m
    {
        GemmDesc ds[1] = {
            mk_desc(adh, adl, w2mdlh, w2mdll, H1, hdh, hdl, w2mdrh, w2mdrl, H1,
                    ND, OD, b2md, nullptr, nullptr, o_d, nullptr, nullptr, F_BIAS)
        };
        GatherDesc t; t.kind=3; t.width=OD; t.nrows=NM;
        t.Xh=nullptr; t.Xl=nullptr; t.Q=ud; t.Base=nullptr;
        t.off=off_m; t.nbr=csr_dst; t.Ch=nullptr; t.Cl=nullptr; t.C=o_m;
        launch_mixed(ds, 1, &t);
    }
}

// round 9
// speedup vs baseline: 1.2106x; 1.2106x over previous
#include <cuda_runtime.h>
#include <cuda_bf16.h>
#include <cstdint>

#define NM 20000
#define ND 8000
#define NE 200000
#define FIN 384
#define HD 512
#define H1 512
#define OD 256

typedef __nv_bfloat16 bf16;
typedef __nv_bfloat162 bf162;

// ---------------- scratch (device globals) ----------------
__device__ bf16 g_mfh[NM*FIN], g_mfl[NM*FIN];
__device__ bf16 g_dfh[ND*FIN], g_dfl[ND*FIN];
__device__ bf16 g_xmh[NM*HD],  g_xml[NM*HD];
__device__ bf16 g_xdh[ND*HD],  g_xdl[ND*HD];
__device__ bf16 g_adh[ND*HD],  g_adl[ND*HD];    // layer1 agg onto disease
__device__ bf16 g_adh2[ND*H1], g_adl2[ND*H1];   // layer2 agg onto disease (separate: avoids WAR)
__device__ bf16 g_hmh[NM*H1],  g_hml[NM*H1];
__device__ bf16 g_hdh[ND*H1],  g_hdl[ND*H1];
__device__ float g_qd[ND*H1];
__device__ float g_base[NM*H1];
__device__ float g_ud[ND*OD];
__device__ bf16 g_wmh[FIN*HD], g_wml[FIN*HD];
__device__ bf16 g_wdh[FIN*HD], g_wdl[FIN*HD];
__device__ bf16 g_w1mdlh[HD*H1], g_w1mdll[HD*H1];
__device__ bf16 g_w1mdrh[HD*H1], g_w1mdrl[HD*H1];
__device__ bf16 g_w1dmlh[HD*H1], g_w1dmll[HD*H1];
__device__ bf16 g_w1dmrh[HD*H1], g_w1dmrl[HD*H1];
__device__ bf16 g_w2mdlh[H1*OD], g_w2mdll[H1*OD];
__device__ bf16 g_w2mdrh[H1*OD], g_w2mdrl[H1*OD];
__device__ bf16 g_w2dmlh[H1*OD], g_w2dmll[H1*OD];
__device__ bf16 g_w2dmrh[H1*OD], g_w2dmrl[H1*OD];
__device__ int g_cnt_m[NM], g_cnt_d[ND];
__device__ int g_off_m[NM+1], g_off_d[ND+1];
__device__ int g_cur_m[NM], g_cur_d[ND];
__device__ int g_csr_src[NE];
__device__ int g_csr_dst[NE];

// ---------------- PTX helpers ----------------
__device__ __forceinline__ void ldsm_x4(uint32_t& r0,uint32_t& r1,uint32_t& r2,uint32_t& r3,uint32_t a){
    asm volatile("ldmatrix.sync.aligned.m8n8.x4.shared.b16 {%0,%1,%2,%3},[%4];"
                 :"=r"(r0),"=r"(r1),"=r"(r2),"=r"(r3):"r"(a));
}
__device__ __forceinline__ void ldsm_x4t(uint32_t& r0,uint32_t& r1,uint32_t& r2,uint32_t& r3,uint32_t a){
    asm volatile("ldmatrix.sync.aligned.m8n8.x4.trans.shared.b16 {%0,%1,%2,%3},[%4];"
                 :"=r"(r0),"=r"(r1),"=r"(r2),"=r"(r3):"r"(a));
}
__device__ __forceinline__ void mma_bf16(float* c, const uint32_t* a, uint32_t b0, uint32_t b1){
    asm volatile("mma.sync.aligned.m16n8k16.row.col.f32.bf16.bf16.f32 "
        "{%0,%1,%2,%3},{%4,%5,%6,%7},{%8,%9},{%0,%1,%2,%3};"
        :"+f"(c[0]),"+f"(c[1]),"+f"(c[2]),"+f"(c[3])
        :"r"(a[0]),"r"(a[1]),"r"(a[2]),"r"(a[3]),"r"(b0),"r"(b1));
}
__device__ __forceinline__ void cpa16(uint32_t d, const void* s, bool p){
    int sz = p ? 16 : 0;
    asm volatile("cp.async.cg.shared.global [%0],[%1],16,%2;"::"r"(d),"l"(s),"r"(sz));
}

// smem geometry (bf16 elements) — R2 proven
#define SA 40
#define SB 136
#define ASZ (128*SA)
#define BSZ (32*SB)
#define STAGE_E (2*ASZ + 2*BSZ)
#define GEMM_SMEM_BYTES (2*STAGE_E*2)

// flags
#define F_BIAS  1
#define F_RELU  2
#define F_GATH  4
#define F_SPLIT 8

struct GemmDesc {
    const bf16 *A1h,*A1l,*B1h,*B1l;
    const bf16 *A2h,*A2l,*B2h,*B2l;
    int K1, K2, M, N;
    const float *bias, *Demb; const int* idx;
    float* C; bf16 *Ch, *Cl;
    int flags;
    int start, tx;
};
struct GemmBatch { GemmDesc g[3]; int n; };

// ---------------- batched bf16x3 tensor-core GEMM (R6-proven) ----------------
__global__ __launch_bounds__(256,2) void mma_gemm_batched(GemmBatch gb)
{
    extern __shared__ bf16 smem[];
    uint32_t sbase = (uint32_t)__cvta_generic_to_shared(smem);
    const int tid  = threadIdx.x;
    const int lane = tid & 31;
    const int wid  = tid >> 5;
    const int wm   = (wid & 3) * 32;
    const int wn   = (wid >> 2) * 64;

    int gi = 0;
    if (gb.n > 1 && (int)blockIdx.x >= gb.g[1].start) gi = 1;
    if (gb.n > 2 && (int)blockIdx.x >= gb.g[2].start) gi = 2;
    const GemmDesc d = gb.g[gi];

    const int rel = blockIdx.x - d.start;
    const int bn  = (rel % d.tx) * 128;
    const int bm  = (rel / d.tx) * 128;
    const int M = d.M, N = d.N;
    const int S1 = d.K1 >> 5, S2 = d.K2 >> 5, S = S1 + S2;

    float acc[2][8][4];
#pragma unroll
    for (int i=0;i<2;i++)
#pragma unroll
        for (int j=0;j<8;j++)
#pragma unroll
            for (int k=0;k<4;k++) acc[i][j][k] = 0.f;

    auto prefetch = [&](int s){
        const bf16 *Ah,*Al,*Bh,*Bl; int K,k0;
        if (s < S1){ Ah=d.A1h; Al=d.A1l; Bh=d.B1h; Bl=d.B1l; K=d.K1; k0=s<<5; }
        else       { Ah=d.A2h; Al=d.A2l; Bh=d.B2h; Bl=d.B2l; K=d.K2; k0=(s-S1)<<5; }
        uint32_t sb = sbase + (uint32_t)((s&1)*STAGE_E*2);
        int ar = tid>>2, ac = (tid&3)*8;
#pragma unroll
        for (int i=0;i<2;i++){
            int row = bm + ar + 64*i;
            bool ok = row < M;
            int sr = ok ? row : 0;
            uint32_t dd = sb + (uint32_t)(((ar+64*i)*SA + ac)*2);
            cpa16(dd,          Ah + (size_t)sr*K + k0 + ac, ok);
            cpa16(dd + ASZ*2,  Al + (size_t)sr*K + k0 + ac, ok);
        }
        int bk = tid>>4, bc = (tid&15)*8;
#pragma unroll
        for (int i=0;i<2;i++){
            int k = bk + 16*i;
            uint32_t dd = sb + (uint32_t)(((2*ASZ) + k*SB + bc)*2);
            size_t go = (size_t)(k0 + k)*N + bn + bc;
            cpa16(dd,          Bh + go, true);
            cpa16(dd + BSZ*2,  Bl + go, true);
        }
        asm volatile("cp.async.commit_group;");
    };

    prefetch(0);
    for (int s=0;s<S;s++){
        if (s+1 < S){
            prefetch(s+1);
            asm volatile("cp.async.wait_group 1;");
        } else {
            asm volatile("cp.async.wait_group 0;");
        }
        __syncthreads();
        uint32_t sb = sbase + (uint32_t)((s&1)*STAGE_E*2);
#pragma unroll
        for (int kk=0;kk<2;kk++){
            const int k16 = kk*16;
            const int loff = (lane>>1)&8;
            uint32_t ah[2][4], al[2][4];
#pragma unroll
            for (int mf=0;mf<2;mf++){
                uint32_t a = sb + (uint32_t)((((wm + mf*16 + (lane&15))*SA) + k16 + loff)*2);
                ldsm_x4(ah[mf][0],ah[mf][1],ah[mf][2],ah[mf][3], a);
                ldsm_x4(al[mf][0],al[mf][1],al[mf][2],al[mf][3], a + ASZ*2);
            }
#pragma unroll
            for (int nb=0;nb<4;nb++){
                uint32_t a = sb + (uint32_t)(((2*ASZ) + (k16 + (lane&15))*SB + wn + nb*16 + loff)*2);
                uint32_t bh[4], bl[4];
                ldsm_x4t(bh[0],bh[1],bh[2],bh[3], a);
                ldsm_x4t(bl[0],bl[1],bl[2],bl[3], a + BSZ*2);
#pragma unroll
                for (int h=0;h<2;h++){
#pragma unroll
                    for (int mf=0;mf<2;mf++){
                        float* c = acc[mf][nb*2+h];
                        mma_bf16(c, ah[mf], bh[2*h], bh[2*h+1]);
                        mma_bf16(c, ah[mf], bl[2*h], bl[2*h+1]);
                        mma_bf16(c, al[mf], bh[2*h], bh[2*h+1]);
                    }
                }
            }
        }
        __syncthreads();
    }

    const int fl = d.flags;
#pragma unroll
    for (int mf=0;mf<2;mf++){
#pragma unroll
        for (int nf=0;nf<8;nf++){
            int col = bn + wn + nf*8 + (lane&3)*2;
#pragma unroll
            for (int half=0;half<2;half++){
                int row = bm + wm + mf*16 + (lane>>2) + half*8;
                if (row >= M) continue;
                float v0 = acc[mf][nf][half*2+0];
                float v1 = acc[mf][nf][half*2+1];
                if (fl & F_BIAS){ v0 += __ldg(&d.bias[col]); v1 += __ldg(&d.bias[col+1]); }
                if (fl & F_GATH){
                    int g = __ldg(&d.idx[row]);
                    const float* e = d.Demb + (size_t)g*N + col;
                    v0 += __ldg(&e[0]); v1 += __ldg(&e[1]);
                }
                if (fl & F_RELU){ v0 = fmaxf(v0,0.f); v1 = fmaxf(v1,0.f); }
                if (fl & F_SPLIT){
                    bf16 h0=__float2bfloat16(v0), h1=__float2bfloat16(v1);
                    bf16 l0=__float2bfloat16(v0-__bfloat162float(h0));
                    bf16 l1=__float2bfloat16(v1-__bfloat162float(h1));
                    *(bf162*)(d.Ch + (size_t)row*N + col) = __halves2bfloat162(h0,h1);
                    *(bf162*)(d.Cl + (size_t)row*N + col) = __halves2bfloat162(l0,l1);
                } else {
                    float2 o; o.x=v0; o.y=v1;
                    *(float2*)(d.C + (size_t)row*N + col) = o;
                }
            }
        }
    }
}

// ---------------- batched split fp32 -> (bf16 hi, bf16 lo) ----------------
struct SplitSet { const float* x[4]; bf16* h[4]; bf16* l[4]; int n4[4]; };
__global__ void bsplit_kernel(SplitSet ss)
{
    int z = blockIdx.y;
    const float* X = ss.x[z]; bf16* H = ss.h[z]; bf16* L = ss.l[z];
    int n4 = ss.n4[z];
    int i = blockIdx.x*blockDim.x + threadIdx.x;
    if (i < n4){
        float4 v = ((const float4*)X)[i];
        bf16 h0=__float2bfloat16(v.x), h1=__float2bfloat16(v.y);
        bf16 h2=__float2bfloat16(v.z), h3=__float2bfloat16(v.w);
        bf16 l0=__float2bfloat16(v.x-__bfloat162float(h0));
        bf16 l1=__float2bfloat16(v.y-__bfloat162float(h1));
        bf16 l2=__float2bfloat16(v.z-__bfloat162float(h2));
        bf16 l3=__float2bfloat16(v.w-__bfloat162float(h3));
        ((bf162*)H)[2*i]   = __halves2bfloat162(h0,h1);
        ((bf162*)H)[2*i+1] = __halves2bfloat162(h2,h3);
        ((bf162*)L)[2*i]   = __halves2bfloat162(l0,l1);
        ((bf162*)L)[2*i+1] = __halves2bfloat162(l2,l3);
    }
}

// ---------------- CSR build ----------------
__global__ void zero_kernel(int* a, int na, int* b, int nb)
{
    int i = blockIdx.x*blockDim.x + threadIdx.x;
    if (i < na) a[i] = 0;
    if (i < nb) b[i] = 0;
}

__global__ void count_edges_kernel(const int* __restrict__ src, const int* __restrict__ dst,
                                   int* __restrict__ cm, int* __restrict__ cd, int E)
{
    int i = blockIdx.x * blockDim.x + threadIdx.x;
    if (i < E) {
        atomicAdd(&cd[dst[i]], 1);
        atomicAdd(&cm[src[i]], 1);
    }
}

__global__ void exscan2_kernel(const int* __restrict__ cnt_d, int* __restrict__ off_d, int* __restrict__ cur_d, int n_d,
                               const int* __restrict__ cnt_m, int* __restrict__ off_m, int* __restrict__ cur_m, int n_m)
{
    const int* cnt; int* off; int* cur; int n;
    if (blockIdx.x == 0){ cnt = cnt_d; off = off_d; cur = cur_d; n = n_d; }
    else               { cnt = cnt_m; off = off_m; cur = cur_m; n = n_m; }
    __shared__ int wsum[32];
    int t = threadIdx.x;
    int chunk = (n + 1023) >> 10;
    int s = t * chunk; if (s > n) s = n;
    int e = s + chunk; if (e > n) e = n;
    int sum = 0;
    for (int i = s; i < e; i++) sum += cnt[i];
    int lane = t & 31, w = t >> 5;
    int v = sum;
#pragma unroll
    for (int dd = 1; dd < 32; dd <<= 1){
        int o = __shfl_up_sync(0xFFFFFFFFu, v, dd);
        if (lane >= dd) v += o;
    }
    if (lane == 31) wsum[w] = v;
    __syncthreads();
    if (w == 0){
        int x = wsum[lane];
#pragma unroll
        for (int dd = 1; dd < 32; dd <<= 1){
            int o = __shfl_up_sync(0xFFFFFFFFu, x, dd);
            if (lane >= dd) x += o;
        }
        wsum[lane] = x;
    }
    __syncthreads();
    int run = v - sum + (w > 0 ? wsum[w-1] : 0);
    for (int i = s; i < e; i++){
        off[i] = run; cur[i] = run; run += cnt[i];
    }
    if (t == 1023) off[n] = run;
}

__global__ void fill_csr_kernel(const int* __restrict__ src, const int* __restrict__ dst,
                                int* __restrict__ cur_m, int* __restrict__ cur_d,
                                int* __restrict__ csr_src, int* __restrict__ csr_dst, int E)
{
    int i = blockIdx.x * blockDim.x + threadIdx.x;
    if (i < E) {
        int m = src[i], d = dst[i];
        int p = atomicAdd(&cur_d[d], 1);
        csr_src[p] = m;
        int q = atomicAdd(&cur_m[m], 1);
        csr_dst[q] = d;
    }
}

// ---------------- segment mean: split-in -> split-out ----------------
template<int WIDTH>
__global__ void seg_mean_split_kernel(const bf16* __restrict__ Xh, const bf16* __restrict__ Xl,
                                      const int* __restrict__ off, const int* __restrict__ nbr,
                                      bf16* __restrict__ Ch, bf16* __restrict__ Cl)
{
    int row = blockIdx.x;
    int t = threadIdx.x;
    int s = off[row], e = off[row + 1];
    float a0=0.f,a1=0.f,a2=0.f,a3=0.f;
    for (int i = s; i < e; i++){
        int nb = __ldg(&nbr[i]);
        const bf162* ph = (const bf162*)(Xh + (size_t)nb*WIDTH);
        const bf162* pl = (const bf162*)(Xl + (size_t)nb*WIDTH);
        bf162 h0 = __ldg(&ph[2*t]), h1 = __ldg(&ph[2*t+1]);
        bf162 l0 = __ldg(&pl[2*t]), l1 = __ldg(&pl[2*t+1]);
        a0 += __bfloat162float(h0.x) + __bfloat162float(l0.x);
        a1 += __bfloat162float(h0.y) + __bfloat162float(l0.y);
        a2 += __bfloat162float(h1.x) + __bfloat162float(l1.x);
        a3 += __bfloat162float(h1.y) + __bfloat162float(l1.y);
    }
    float inv = (e > s) ? 1.0f/(float)(e - s) : 0.0f;
    a0 *= inv; a1 *= inv; a2 *= inv; a3 *= inv;
    bf16 h0=__float2bfloat16(a0), h1=__float2bfloat16(a1);
    bf16 h2=__float2bfloat16(a2), h3=__float2bfloat16(a3);
    bf16 l0=__float2bfloat16(a0-__bfloat162float(h0));
    bf16 l1=__float2bfloat16(a1-__bfloat162float(h1));
    bf16 l2=__float2bfloat16(a2-__bfloat162float(h2));
    bf16 l3=__float2bfloat16(a3-__bfloat162float(h3));
    bf162* och = (bf162*)(Ch + (size_t)row*WIDTH);
    bf162* ocl = (bf162*)(Cl + (size_t)row*WIDTH);
    och[2*t]   = __halves2bfloat162(h0,h1);
    och[2*t+1] = __halves2bfloat162(h2,h3);
    ocl[2*t]   = __halves2bfloat162(l0,l1);
    ocl[2*t+1] = __halves2bfloat162(l2,l3);
}

// ---------------- seg mean (f32 msgs) + base + relu -> split out ----------------
template<int WIDTH>
__global__ void seg_relu_split_kernel(const float* __restrict__ Q, const float* __restrict__ Base,
                                      const int* __restrict__ off, const int* __restrict__ nbr,
                                      bf16* __restrict__ Ch, bf16* __restrict__ Cl)
{
    int row = blockIdx.x;
    int t = threadIdx.x;
    int s = off[row], e = off[row + 1];
    float4 acc = make_float4(0.f,0.f,0.f,0.f);
    for (int i = s; i < e; i++){
        int nb = __ldg(&nbr[i]);
        float4 v = __ldg((const float4*)(Q + (size_t)nb*WIDTH) + t);
        acc.x += v.x; acc.y += v.y; acc.z += v.z; acc.w += v.w;
    }
    float inv = (e > s) ? 1.0f/(float)(e - s) : 0.0f;
    float4 b = __ldg((const float4*)(Base + (size_t)row*WIDTH) + t);
    float x0 = fmaxf(b.x + acc.x*inv, 0.f);
    float x1 = fmaxf(b.y + acc.y*inv, 0.f);
    float x2 = fmaxf(b.z + acc.z*inv, 0.f);
    float x3 = fmaxf(b.w + acc.w*inv, 0.f);
    bf16 h0=__float2bfloat16(x0), h1=__float2bfloat16(x1);
    bf16 h2=__float2bfloat16(x2), h3=__float2bfloat16(x3);
    bf16 l0=__float2bfloat16(x0-__bfloat162float(h0));
    bf16 l1=__float2bfloat16(x1-__bfloat162float(h1));
    bf16 l2=__float2bfloat16(x2-__bfloat162float(h2));
    bf16 l3=__float2bfloat16(x3-__bfloat162float(h3));
    bf162* och = (bf162*)(Ch + (size_t)row*WIDTH);
    bf162* ocl = (bf162*)(Cl + (size_t)row*WIDTH);
    och[2*t]   = __halves2bfloat162(h0,h1);
    och[2*t+1] = __halves2bfloat162(h2,h3);
    ocl[2*t]   = __halves2bfloat162(l0,l1);
    ocl[2*t+1] = __halves2bfloat162(l2,l3);
}

// ---------------- segment mean: f32-in, accumulate into f32 out ----------------
template <int WIDTH>
__global__ void seg_mean_acc_kernel(const float* __restrict__ X, const int* __restrict__ off,
                                    const int* __restrict__ nbr, float* __restrict__ C)
{
    int row = blockIdx.x;
    int t = threadIdx.x;
    int s = off[row], e = off[row + 1];
    float4 acc = make_float4(0.f, 0.f, 0.f, 0.f);
    for (int i = s; i < e; i++) {
        int nb = __ldg(&nbr[i]);
        float4 v = __ldg((const float4*)(X + (size_t)nb * WIDTH) + t);
        acc.x += v.x; acc.y += v.y; acc.z += v.z; acc.w += v.w;
    }
    float inv = (e > s) ? 1.0f / (float)(e - s) : 0.0f;
    float4* cp = (float4*)(C + (size_t)row * WIDTH) + t;
    float4 o = *cp;
    o.x += acc.x*inv; o.y += acc.y*inv; o.z += acc.z*inv; o.w += acc.w*inv;
    *cp = o;
}

// ---------------- host orchestration ----------------
#define SYM(p, s) cudaGetSymbolAddress((void**)&(p), s)

static inline GemmDesc mk_desc(
    const bf16* A1h, const bf16* A1l, const bf16* B1h, const bf16* B1l, int K1,
    const bf16* A2h, const bf16* A2l, const bf16* B2h, const bf16* B2l, int K2,
    int M, int N, const float* bias, const float* Demb, const int* idx,
    float* C, bf16* Ch, bf16* Cl, int flags)
{
    GemmDesc d;
    d.A1h=A1h; d.A1l=A1l; d.B1h=B1h; d.B1l=B1l; d.K1=K1;
    d.A2h=A2h; d.A2l=A2l; d.B2h=B2h; d.B2l=B2l; d.K2=K2;
    d.M=M; d.N=N; d.bias=bias; d.Demb=Demb; d.idx=idx;
    d.C=C; d.Ch=Ch; d.Cl=Cl; d.flags=flags;
    d.start=0; d.tx=N/128;
    return d;
}

static inline void launch_batch(GemmDesc* descs, int n, cudaStream_t st)
{
    GemmBatch gb;
    int total = 0;
    for (int i = 0; i < n; i++){
        descs[i].start = total;
        total += descs[i].tx * ((descs[i].M + 127)/128);
        gb.g[i] = descs[i];
    }
    for (int i = n; i < 3; i++){ gb.g[i] = descs[n-1]; gb.g[i].start = 0x7FFFFFFF; }
    gb.n = n;
    mma_gemm_batched<<<total, 256, GEMM_SMEM_BYTES, st>>>(gb);
}

// static aux resources (created on first, uncaptured, call)
struct Aux {
    cudaStream_t s2;
    cudaEvent_t ev[10];
    Aux(){
        cudaStreamCreateWithFlags(&s2, cudaStreamNonBlocking);
        for (int i = 0; i < 10; i++)
            cudaEventCreateWithFlags(&ev[i], cudaEventDisableTiming);
    }
};

extern "C" void kernel_launch(void* const* d_in, const int* in_sizes, int n_in,
                              void* d_out, int out_size)
{
    static Aux aux;

    // pick the stream that is actually being captured (or per-thread default otherwise)
    cudaStream_t ms = cudaStreamPerThread;
    {
        cudaStreamCaptureStatus st = cudaStreamCaptureStatusNone;
        if (cudaStreamIsCapturing(cudaStreamPerThread, &st) == cudaSuccess &&
            st == cudaStreamCaptureStatusActive) {
            ms = cudaStreamPerThread;
        } else {
            cudaGetLastError();
            st = cudaStreamCaptureStatusNone;
            if (cudaStreamIsCapturing(cudaStreamLegacy, &st) == cudaSuccess &&
                st == cudaStreamCaptureStatusActive) {
                ms = cudaStreamLegacy;
            }
            cudaGetLastError();
        }
    }
    cudaStream_t s2 = aux.s2;

    const float* mf   = (const float*)d_in[0];
    const float* df   = (const float*)d_in[1];
    const int*   mid  = (const int*)d_in[2];
    const int*   did  = (const int*)d_in[3];
    const int*   esrc = (const int*)d_in[4];
    const int*   edst = (const int*)d_in[5];
    const float* Wm   = (const float*)d_in[6];
    const float* bm   = (const float*)d_in[7];
    const float* Wd   = (const float*)d_in[8];
    const float* bd   = (const float*)d_in[9];
    const float* memb = (const float*)d_in[10];
    const float* demb = (const float*)d_in[11];
    const float* W1mdl = (const float*)d_in[12];
    const float* b1md  = (const float*)d_in[13];
    const float* W1mdr = (const float*)d_in[14];
    const float* W1dml = (const float*)d_in[15];
    const float* b1dm  = (const float*)d_in[16];
    const float* W1dmr = (const float*)d_in[17];
    const float* W2mdl = (const float*)d_in[18];
    const float* b2md  = (const float*)d_in[19];
    const float* W2mdr = (const float*)d_in[20];
    const float* W2dml = (const float*)d_in[21];
    const float* b2dm  = (const float*)d_in[22];
    const float* W2dmr = (const float*)d_in[23];

    float* out = (float*)d_out;
    float* o_m = out;
    float* o_d = out + (size_t)NM * OD;

    bf16 *mfh,*mfl,*dfh,*dfl,*xmh,*xml,*xdh,*xdl,*adh,*adl,*adh2,*adl2,*hmh,*hml,*hdh,*hdl;
    bf16 *wmh,*wml,*wdh,*wdl;
    bf16 *w1mdlh,*w1mdll,*w1mdrh,*w1mdrl,*w1dmlh,*w1dmll,*w1dmrh,*w1dmrl;
    bf16 *w2mdlh,*w2mdll,*w2mdrh,*w2mdrl,*w2dmlh,*w2dmll,*w2dmrh,*w2dmrl;
    float *qd,*basem,*ud;
    int *cnt_m,*cnt_d,*off_m,*off_d,*cur_m,*cur_d,*csr_src,*csr_dst;
    SYM(mfh,g_mfh); SYM(mfl,g_mfl); SYM(dfh,g_dfh); SYM(dfl,g_dfl);
    SYM(xmh,g_xmh); SYM(xml,g_xml); SYM(xdh,g_xdh); SYM(xdl,g_xdl);
    SYM(adh,g_adh); SYM(adl,g_adl); SYM(adh2,g_adh2); SYM(adl2,g_adl2);
    SYM(hmh,g_hmh); SYM(hml,g_hml); SYM(hdh,g_hdh); SYM(hdl,g_hdl);
    SYM(wmh,g_wmh); SYM(wml,g_wml); SYM(wdh,g_wdh); SYM(wdl,g_wdl);
    SYM(w1mdlh,g_w1mdlh); SYM(w1mdll,g_w1mdll); SYM(w1mdrh,g_w1mdrh); SYM(w1mdrl,g_w1mdrl);
    SYM(w1dmlh,g_w1dmlh); SYM(w1dmll,g_w1dmll); SYM(w1dmrh,g_w1dmrh); SYM(w1dmrl,g_w1dmrl);
    SYM(w2mdlh,g_w2mdlh); SYM(w2mdll,g_w2mdll); SYM(w2mdrh,g_w2mdrh); SYM(w2mdrl,g_w2mdrl);
    SYM(w2dmlh,g_w2dmlh); SYM(w2dmll,g_w2dmll); SYM(w2dmrh,g_w2dmrh); SYM(w2dmrl,g_w2dmrl);
    SYM(qd,g_qd); SYM(basem,g_base); SYM(ud,g_ud);
    SYM(cnt_m,g_cnt_m); SYM(cnt_d,g_cnt_d); SYM(off_m,g_off_m); SYM(off_d,g_off_d);
    SYM(cur_m,g_cur_m); SYM(cur_d,g_cur_d); SYM(csr_src,g_csr_src); SYM(csr_dst,g_csr_dst);

    cudaFuncSetAttribute(mma_gemm_batched, cudaFuncAttributeMaxDynamicSharedMemorySize, GEMM_SMEM_BYTES);

    // ---- fork s2: CSR chain (all CSR consumers live on s2) ----
    cudaEventRecord(aux.ev[0], ms);
    cudaStreamWaitEvent(s2, aux.ev[0], 0);
    zero_kernel<<<(NM + 255)/256, 256, 0, s2>>>(cnt_m, NM, cnt_d, ND);
    count_edges_kernel<<<(NE + 255) / 256, 256, 0, s2>>>(esrc, edst, cnt_m, cnt_d, NE);
    exscan2_kernel<<<2, 1024, 0, s2>>>(cnt_d, off_d, cur_d, ND, cnt_m, off_m, cur_m, NM);
    fill_csr_kernel<<<(NE + 255) / 256, 256, 0, s2>>>(esrc, edst, cur_m, cur_d, csr_src, csr_dst, NE);

    // ---- main: splits ----
    {
        SplitSet s1;
        s1.x[0]=mf; s1.h[0]=mfh; s1.l[0]=mfl; s1.n4[0]=NM*FIN/4;
        s1.x[1]=df; s1.h[1]=dfh; s1.l[1]=dfl; s1.n4[1]=ND*FIN/4;
        s1.x[2]=Wm; s1.h[2]=wmh; s1.l[2]=wml; s1.n4[2]=FIN*HD/4;
        s1.x[3]=Wd; s1.h[3]=wdh; s1.l[3]=wdl; s1.n4[3]=FIN*HD/4;
        int mx = NM*FIN/4;
        bsplit_kernel<<<dim3((mx + 255)/256, 4), 256, 0, ms>>>(s1);

        SplitSet s2s;
        s2s.x[0]=W1mdl; s2s.h[0]=w1mdlh; s2s.l[0]=w1mdll; s2s.n4[0]=HD*H1/4;
        s2s.x[1]=W1mdr; s2s.h[1]=w1mdrh; s2s.l[1]=w1mdrl; s2s.n4[1]=HD*H1/4;
        s2s.x[2]=W1dml; s2s.h[2]=w1dmlh; s2s.l[2]=w1dmll; s2s.n4[2]=HD*H1/4;
        s2s.x[3]=W1dmr; s2s.h[3]=w1dmrh; s2s.l[3]=w1dmrl; s2s.n4[3]=HD*H1/4;
        bsplit_kernel<<<dim3((HD*H1/4 + 255)/256, 4), 256, 0, ms>>>(s2s);

        SplitSet s3;
        s3.x[0]=W2mdl; s3.h[0]=w2mdlh; s3.l[0]=w2mdll; s3.n4[0]=H1*OD/4;
        s3.x[1]=W2mdr; s3.h[1]=w2mdrh; s3.l[1]=w2mdrl; s3.n4[1]=H1*OD/4;
        s3.x[2]=W2dml; s3.h[2]=w2dmlh; s3.l[2]=w2dmll; s3.n4[2]=H1*OD/4;
        s3.x[3]=W2dmr; s3.h[3]=w2dmrh; s3.l[3]=w2dmrl; s3.n4[3]=H1*OD/4;
        bsplit_kernel<<<dim3((H1*OD/4 + 255)/256, 4), 256, 0, ms>>>(s3);
    }

    // ---- main: L1 encoders ----
    {
        GemmDesc ds[2] = {
            mk_desc(mfh, mfl, wmh, wml, FIN, 0,0,0,0, 0,
                    NM, HD, bm, memb, mid, nullptr, xmh, xml, F_BIAS|F_GATH|F_SPLIT),
            mk_desc(dfh, dfl, wdh, wdl, FIN, 0,0,0,0, 0,
                    ND, HD, bd, demb, did, nullptr, xdh, xdl, F_BIAS|F_GATH|F_SPLIT)
        };
        launch_batch(ds, 2, ms);
    }

    // fork: x ready -> s2 gather layer1
    cudaEventRecord(aux.ev[1], ms);
    cudaStreamWaitEvent(s2, aux.ev[1], 0);
    seg_mean_split_kernel<HD><<<ND, HD/4, 0, s2>>>(xmh, xml, off_d, csr_src, adh, adl);
    cudaEventRecord(aux.ev[2], s2);   // adh/adl (layer1) ready

    // ---- main: qd + base GEMMs (concurrent with gather above) ----
    {
        GemmDesc ds[2] = {
            mk_desc(xdh, xdl, w1dmlh, w1dmll, HD, 0,0,0,0, 0,
                    ND, H1, nullptr, nullptr, nullptr, qd, nullptr, nullptr, 0),
            mk_desc(xmh, xml, w1dmrh, w1dmrl, HD, 0,0,0,0, 0,
                    NM, H1, b1dm, nullptr, nullptr, basem, nullptr, nullptr, F_BIAS)
        };
        launch_batch(ds, 2, ms);
    }
    cudaEventRecord(aux.ev[3], ms);   // qd + base ready

    // s2: relu-gather -> h_m (needs qd/base)
    cudaStreamWaitEvent(s2, aux.ev[3], 0);
    seg_relu_split_kernel<H1><<<NM, H1/4, 0, s2>>>(qd, basem, off_m, csr_dst, hmh, hml);
    cudaEventRecord(aux.ev[4], s2);   // h_m ready
    // s2: gather h_m -> adh2/adl2 (separate buffers: no WAR with L1md's read of adh/adl)
    seg_mean_split_kernel<H1><<<ND, H1/4, 0, s2>>>(hmh, hml, off_d, csr_src, adh2, adl2);
    cudaEventRecord(aux.ev[5], s2);   // adh2/adl2 (layer2) ready

    // ---- main: L1md dual-K GEMM -> h_d (needs adh/adl from ev2) ----
    cudaStreamWaitEvent(ms, aux.ev[2], 0);
    {
        GemmDesc ds[1] = {
            mk_desc(adh, adl, w1mdlh, w1mdll, HD, xdh, xdl, w1mdrh, w1mdrl, HD,
                    ND, H1, b1md, nullptr, nullptr, nullptr, hdh, hdl, F_BIAS|F_RELU|F_SPLIT)
        };
        launch_batch(ds, 1, ms);
    }

    // ---- main: L4 GEMMs (ud needs h_d; o_m needs h_m from ev4) ----
    cudaStreamWaitEvent(ms, aux.ev[4], 0);
    {
        GemmDesc ds[2] = {
            mk_desc(hdh, hdl, w2dmlh, w2dmll, H1, 0,0,0,0, 0,
                    ND, OD, nullptr, nullptr, nullptr, ud, nullptr, nullptr, 0),
            mk_desc(hmh, hml, w2dmrh, w2dmrl, H1, 0,0,0,0, 0,
                    NM, OD, b2dm, nullptr, nullptr, o_m, nullptr, nullptr, F_BIAS)
        };
        launch_batch(ds, 2, ms);
    }
    cudaEventRecord(aux.ev[6], ms);   // ud + o_m base ready

    // s2: acc-gather ud -> o_m (needs ud/o_m from ev6)
    cudaStreamWaitEvent(s2, aux.ev[6], 0);
    seg_mean_acc_kernel<OD><<<NM, OD/4, 0, s2>>>(ud, off_m, csr_dst, o_m);
    cudaEventRecord(aux.ev[7], s2);

    // ---- main: L5 dual-K GEMM -> o_d (needs adh2/adl2 from ev5) ----
    cudaStreamWaitEvent(ms, aux.ev[5], 0);
    {
        GemmDesc ds[1] = {
            mk_desc(adh2, adl2, w2mdlh, w2mdll, H1, hdh, hdl, w2mdrh, w2mdrl, H1,
                    ND, OD, b2md, nullptr, nullptr, o_d, nullptr, nullptr, F_BIAS)
        };
        launch_batch(ds, 1, ms);
    }

    // final join: main waits for s2 tail
    cudaStreamWaitEvent(ms, aux.ev[7], 0);
}

// round 10
// speedup vs baseline: 1.2457x; 1.0290x over previous
#include <cuda_runtime.h>
#include <cuda_bf16.h>
#include <cstdint>

#define NM 20000
#define ND 8000
#define NE 200000
#define FIN 384
#define HD 512
#define H1 512
#define OD 256

typedef __nv_bfloat16 bf16;
typedef __nv_bfloat162 bf162;

// ---------------- scratch (device globals) ----------------
__device__ bf16 g_mfh[NM*FIN], g_mfl[NM*FIN];
__device__ bf16 g_dfh[ND*FIN], g_dfl[ND*FIN];
__device__ bf16 g_xmh[NM*HD],  g_xml[NM*HD];
__device__ bf16 g_xdh[ND*HD],  g_xdl[ND*HD];
__device__ bf16 g_adh[ND*HD],  g_adl[ND*HD];    // layer1 agg onto disease
__device__ bf16 g_adh2[ND*H1], g_adl2[ND*H1];   // layer2 agg onto disease
__device__ bf16 g_hmh[NM*H1],  g_hml[NM*H1];
__device__ bf16 g_hdh[ND*H1],  g_hdl[ND*H1];
__device__ float g_qd[ND*H1];
__device__ float g_base[NM*H1];
__device__ float g_ud[ND*OD];
__device__ bf16 g_wmh[FIN*HD], g_wml[FIN*HD];
__device__ bf16 g_wdh[FIN*HD], g_wdl[FIN*HD];
__device__ bf16 g_w1mdlh[HD*H1], g_w1mdll[HD*H1];
__device__ bf16 g_w1mdrh[HD*H1], g_w1mdrl[HD*H1];
__device__ bf16 g_w1dmlh[HD*H1], g_w1dmll[HD*H1];
__device__ bf16 g_w1dmrh[HD*H1], g_w1dmrl[HD*H1];
__device__ bf16 g_w2mdlh[H1*OD], g_w2mdll[H1*OD];
__device__ bf16 g_w2mdrh[H1*OD], g_w2mdrl[H1*OD];
__device__ bf16 g_w2dmlh[H1*OD], g_w2dmll[H1*OD];
__device__ bf16 g_w2dmrh[H1*OD], g_w2dmrl[H1*OD];
__device__ int g_cnt_m[NM], g_cnt_d[ND];
__device__ int g_off_m[NM+1], g_off_d[ND+1];
__device__ int g_cur_m[NM], g_cur_d[ND];
__device__ int g_csr_src[NE];
__device__ int g_csr_dst[NE];

// ---------------- PTX helpers ----------------
__device__ __forceinline__ void ldsm_x4(uint32_t& r0,uint32_t& r1,uint32_t& r2,uint32_t& r3,uint32_t a){
    asm volatile("ldmatrix.sync.aligned.m8n8.x4.shared.b16 {%0,%1,%2,%3},[%4];"
                 :"=r"(r0),"=r"(r1),"=r"(r2),"=r"(r3):"r"(a));
}
__device__ __forceinline__ void ldsm_x4t(uint32_t& r0,uint32_t& r1,uint32_t& r2,uint32_t& r3,uint32_t a){
    asm volatile("ldmatrix.sync.aligned.m8n8.x4.trans.shared.b16 {%0,%1,%2,%3},[%4];"
                 :"=r"(r0),"=r"(r1),"=r"(r2),"=r"(r3):"r"(a));
}
__device__ __forceinline__ void mma_bf16(float* c, const uint32_t* a, uint32_t b0, uint32_t b1){
    asm volatile("mma.sync.aligned.m16n8k16.row.col.f32.bf16.bf16.f32 "
        "{%0,%1,%2,%3},{%4,%5,%6,%7},{%8,%9},{%0,%1,%2,%3};"
        :"+f"(c[0]),"+f"(c[1]),"+f"(c[2]),"+f"(c[3])
        :"r"(a[0]),"r"(a[1]),"r"(a[2]),"r"(a[3]),"r"(b0),"r"(b1));
}
__device__ __forceinline__ void cpa16(uint32_t d, const void* s, bool p){
    int sz = p ? 16 : 0;
    asm volatile("cp.async.cg.shared.global [%0],[%1],16,%2;"::"r"(d),"l"(s),"r"(sz));
}

// smem geometry (bf16 elements) — R2 proven
#define SA 40
#define SB 136
#define ASZ (128*SA)
#define BSZ (32*SB)
#define STAGE_E (2*ASZ + 2*BSZ)
#define GEMM_SMEM_BYTES (2*STAGE_E*2)

// flags
#define F_BIAS  1
#define F_RELU  2
#define F_GATH  4
#define F_SPLIT 8

struct GemmDesc {
    const bf16 *A1h,*A1l,*B1h,*B1l;
    const bf16 *A2h,*A2l,*B2h,*B2l;
    int K1, K2, M, N;
    const float *bias, *Demb; const int* idx;
    float* C; bf16 *Ch, *Cl;
    int flags;
    int start, tx;
};
struct GemmBatch { GemmDesc g[3]; int n; };

// ---------------- batched bf16x3 tensor-core GEMM (R6-proven) ----------------
__global__ __launch_bounds__(256,2) void mma_gemm_batched(GemmBatch gb)
{
    extern __shared__ bf16 smem[];
    uint32_t sbase = (uint32_t)__cvta_generic_to_shared(smem);
    const int tid  = threadIdx.x;
    const int lane = tid & 31;
    const int wid  = tid >> 5;
    const int wm   = (wid & 3) * 32;
    const int wn   = (wid >> 2) * 64;

    int gi = 0;
    if (gb.n > 1 && (int)blockIdx.x >= gb.g[1].start) gi = 1;
    if (gb.n > 2 && (int)blockIdx.x >= gb.g[2].start) gi = 2;
    const GemmDesc d = gb.g[gi];

    const int rel = blockIdx.x - d.start;
    const int bn  = (rel % d.tx) * 128;
    const int bm  = (rel / d.tx) * 128;
    const int M = d.M, N = d.N;
    const int S1 = d.K1 >> 5, S2 = d.K2 >> 5, S = S1 + S2;

    float acc[2][8][4];
#pragma unroll
    for (int i=0;i<2;i++)
#pragma unroll
        for (int j=0;j<8;j++)
#pragma unroll
            for (int k=0;k<4;k++) acc[i][j][k] = 0.f;

    auto prefetch = [&](int s){
        const bf16 *Ah,*Al,*Bh,*Bl; int K,k0;
        if (s < S1){ Ah=d.A1h; Al=d.A1l; Bh=d.B1h; Bl=d.B1l; K=d.K1; k0=s<<5; }
        else       { Ah=d.A2h; Al=d.A2l; Bh=d.B2h; Bl=d.B2l; K=d.K2; k0=(s-S1)<<5; }
        uint32_t sb = sbase + (uint32_t)((s&1)*STAGE_E*2);
        int ar = tid>>2, ac = (tid&3)*8;
#pragma unroll
        for (int i=0;i<2;i++){
            int row = bm + ar + 64*i;
            bool ok = row < M;
            int sr = ok ? row : 0;
            uint32_t dd = sb + (uint32_t)(((ar+64*i)*SA + ac)*2);
            cpa16(dd,          Ah + (size_t)sr*K + k0 + ac, ok);
            cpa16(dd + ASZ*2,  Al + (size_t)sr*K + k0 + ac, ok);
        }
        int bk = tid>>4, bc = (tid&15)*8;
#pragma unroll
        for (int i=0;i<2;i++){
            int k = bk + 16*i;
            uint32_t dd = sb + (uint32_t)(((2*ASZ) + k*SB + bc)*2);
            size_t go = (size_t)(k0 + k)*N + bn + bc;
            cpa16(dd,          Bh + go, true);
            cpa16(dd + BSZ*2,  Bl + go, true);
        }
        asm volatile("cp.async.commit_group;");
    };

    prefetch(0);
    for (int s=0;s<S;s++){
        if (s+1 < S){
            prefetch(s+1);
            asm volatile("cp.async.wait_group 1;");
        } else {
            asm volatile("cp.async.wait_group 0;");
        }
        __syncthreads();
        uint32_t sb = sbase + (uint32_t)((s&1)*STAGE_E*2);
#pragma unroll
        for (int kk=0;kk<2;kk++){
            const int k16 = kk*16;
            const int loff = (lane>>1)&8;
            uint32_t ah[2][4], al[2][4];
#pragma unroll
            for (int mf=0;mf<2;mf++){
                uint32_t a = sb + (uint32_t)((((wm + mf*16 + (lane&15))*SA) + k16 + loff)*2);
                ldsm_x4(ah[mf][0],ah[mf][1],ah[mf][2],ah[mf][3], a);
                ldsm_x4(al[mf][0],al[mf][1],al[mf][2],al[mf][3], a + ASZ*2);
            }
#pragma unroll
            for (int nb=0;nb<4;nb++){
                uint32_t a = sb + (uint32_t)(((2*ASZ) + (k16 + (lane&15))*SB + wn + nb*16 + loff)*2);
                uint32_t bh[4], bl[4];
                ldsm_x4t(bh[0],bh[1],bh[2],bh[3], a);
                ldsm_x4t(bl[0],bl[1],bl[2],bl[3], a + BSZ*2);
#pragma unroll
                for (int h=0;h<2;h++){
#pragma unroll
                    for (int mf=0;mf<2;mf++){
                        float* c = acc[mf][nb*2+h];
                        mma_bf16(c, ah[mf], bh[2*h], bh[2*h+1]);
                        mma_bf16(c, ah[mf], bl[2*h], bl[2*h+1]);
                        mma_bf16(c, al[mf], bh[2*h], bh[2*h+1]);
                    }
                }
            }
        }
        __syncthreads();
    }

    const int fl = d.flags;
#pragma unroll
    for (int mf=0;mf<2;mf++){
#pragma unroll
        for (int nf=0;nf<8;nf++){
            int col = bn + wn + nf*8 + (lane&3)*2;
#pragma unroll
            for (int half=0;half<2;half++){
                int row = bm + wm + mf*16 + (lane>>2) + half*8;
                if (row >= M) continue;
                float v0 = acc[mf][nf][half*2+0];
                float v1 = acc[mf][nf][half*2+1];
                if (fl & F_BIAS){ v0 += __ldg(&d.bias[col]); v1 += __ldg(&d.bias[col+1]); }
                if (fl & F_GATH){
                    int g = __ldg(&d.idx[row]);
                    const float* e = d.Demb + (size_t)g*N + col;
                    v0 += __ldg(&e[0]); v1 += __ldg(&e[1]);
                }
                if (fl & F_RELU){ v0 = fmaxf(v0,0.f); v1 = fmaxf(v1,0.f); }
                if (fl & F_SPLIT){
                    bf16 h0=__float2bfloat16(v0), h1=__float2bfloat16(v1);
                    bf16 l0=__float2bfloat16(v0-__bfloat162float(h0));
                    bf16 l1=__float2bfloat16(v1-__bfloat162float(h1));
                    *(bf162*)(d.Ch + (size_t)row*N + col) = __halves2bfloat162(h0,h1);
                    *(bf162*)(d.Cl + (size_t)row*N + col) = __halves2bfloat162(l0,l1);
                } else {
                    float2 o; o.x=v0; o.y=v1;
                    *(float2*)(d.C + (size_t)row*N + col) = o;
                }
            }
        }
    }
}

// ---------------- batched split fp32 -> (bf16 hi, bf16 lo) ----------------
struct SplitSet { const float* x[4]; bf16* h[4]; bf16* l[4]; int n4[4]; };
__global__ void bsplit_kernel(SplitSet ss)
{
    int z = blockIdx.y;
    const float* X = ss.x[z]; bf16* H = ss.h[z]; bf16* L = ss.l[z];
    int n4 = ss.n4[z];
    int i = blockIdx.x*blockDim.x + threadIdx.x;
    if (i < n4){
        float4 v = ((const float4*)X)[i];
        bf16 h0=__float2bfloat16(v.x), h1=__float2bfloat16(v.y);
        bf16 h2=__float2bfloat16(v.z), h3=__float2bfloat16(v.w);
        bf16 l0=__float2bfloat16(v.x-__bfloat162float(h0));
        bf16 l1=__float2bfloat16(v.y-__bfloat162float(h1));
        bf16 l2=__float2bfloat16(v.z-__bfloat162float(h2));
        bf16 l3=__float2bfloat16(v.w-__bfloat162float(h3));
        ((bf162*)H)[2*i]   = __halves2bfloat162(h0,h1);
        ((bf162*)H)[2*i+1] = __halves2bfloat162(h2,h3);
        ((bf162*)L)[2*i]   = __halves2bfloat162(l0,l1);
        ((bf162*)L)[2*i+1] = __halves2bfloat162(l2,l3);
    }
}

// ---------------- CSR build ----------------
__global__ void zero_kernel(int* a, int na, int* b, int nb)
{
    int i = blockIdx.x*blockDim.x + threadIdx.x;
    if (i < na) a[i] = 0;
    if (i < nb) b[i] = 0;
}

__global__ void count_edges_kernel(const int* __restrict__ src, const int* __restrict__ dst,
                                   int* __restrict__ cm, int* __restrict__ cd, int E)
{
    int i = blockIdx.x * blockDim.x + threadIdx.x;
    if (i < E) {
        atomicAdd(&cd[dst[i]], 1);
        atomicAdd(&cm[src[i]], 1);
    }
}

__global__ void exscan2_kernel(const int* __restrict__ cnt_d, int* __restrict__ off_d, int* __restrict__ cur_d, int n_d,
                               const int* __restrict__ cnt_m, int* __restrict__ off_m, int* __restrict__ cur_m, int n_m)
{
    const int* cnt; int* off; int* cur; int n;
    if (blockIdx.x == 0){ cnt = cnt_d; off = off_d; cur = cur_d; n = n_d; }
    else               { cnt = cnt_m; off = off_m; cur = cur_m; n = n_m; }
    __shared__ int wsum[32];
    int t = threadIdx.x;
    int chunk = (n + 1023) >> 10;
    int s = t * chunk; if (s > n) s = n;
    int e = s + chunk; if (e > n) e = n;
    int sum = 0;
    for (int i = s; i < e; i++) sum += cnt[i];
    int lane = t & 31, w = t >> 5;
    int v = sum;
#pragma unroll
    for (int dd = 1; dd < 32; dd <<= 1){
        int o = __shfl_up_sync(0xFFFFFFFFu, v, dd);
        if (lane >= dd) v += o;
    }
    if (lane == 31) wsum[w] = v;
    __syncthreads();
    if (w == 0){
        int x = wsum[lane];
#pragma unroll
        for (int dd = 1; dd < 32; dd <<= 1){
            int o = __shfl_up_sync(0xFFFFFFFFu, x, dd);
            if (lane >= dd) x += o;
        }
        wsum[lane] = x;
    }
    __syncthreads();
    int run = v - sum + (w > 0 ? wsum[w-1] : 0);
    for (int i = s; i < e; i++){
        off[i] = run; cur[i] = run; run += cnt[i];
    }
    if (t == 1023) off[n] = run;
}

__global__ void fill_csr_kernel(const int* __restrict__ src, const int* __restrict__ dst,
                                int* __restrict__ cur_m, int* __restrict__ cur_d,
                                int* __restrict__ csr_src, int* __restrict__ csr_dst, int E)
{
    int i = blockIdx.x * blockDim.x + threadIdx.x;
    if (i < E) {
        int m = src[i], d = dst[i];
        int p = atomicAdd(&cur_d[d], 1);
        csr_src[p] = m;
        int q = atomicAdd(&cur_m[m], 1);
        csr_dst[q] = d;
    }
}

// ---------------- segment mean: split-in -> split-out ----------------
template<int WIDTH>
__global__ void seg_mean_split_kernel(const bf16* __restrict__ Xh, const bf16* __restrict__ Xl,
                                      const int* __restrict__ off, const int* __restrict__ nbr,
                                      bf16* __restrict__ Ch, bf16* __restrict__ Cl)
{
    int row = blockIdx.x;
    int t = threadIdx.x;
    int s = off[row], e = off[row + 1];
    float a0=0.f,a1=0.f,a2=0.f,a3=0.f;
    for (int i = s; i < e; i++){
        int nb = __ldg(&nbr[i]);
        const bf162* ph = (const bf162*)(Xh + (size_t)nb*WIDTH);
        const bf162* pl = (const bf162*)(Xl + (size_t)nb*WIDTH);
        bf162 h0 = __ldg(&ph[2*t]), h1 = __ldg(&ph[2*t+1]);
        bf162 l0 = __ldg(&pl[2*t]), l1 = __ldg(&pl[2*t+1]);
        a0 += __bfloat162float(h0.x) + __bfloat162float(l0.x);
        a1 += __bfloat162float(h0.y) + __bfloat162float(l0.y);
        a2 += __bfloat162float(h1.x) + __bfloat162float(l1.x);
        a3 += __bfloat162float(h1.y) + __bfloat162float(l1.y);
    }
    float inv = (e > s) ? 1.0f/(float)(e - s) : 0.0f;
    a0 *= inv; a1 *= inv; a2 *= inv; a3 *= inv;
    bf16 h0=__float2bfloat16(a0), h1=__float2bfloat16(a1);
    bf16 h2=__float2bfloat16(a2), h3=__float2bfloat16(a3);
    bf16 l0=__float2bfloat16(a0-__bfloat162float(h0));
    bf16 l1=__float2bfloat16(a1-__bfloat162float(h1));
    bf16 l2=__float2bfloat16(a2-__bfloat162float(h2));
    bf16 l3=__float2bfloat16(a3-__bfloat162float(h3));
    bf162* och = (bf162*)(Ch + (size_t)row*WIDTH);
    bf162* ocl = (bf162*)(Cl + (size_t)row*WIDTH);
    och[2*t]   = __halves2bfloat162(h0,h1);
    och[2*t+1] = __halves2bfloat162(h2,h3);
    ocl[2*t]   = __halves2bfloat162(l0,l1);
    ocl[2*t+1] = __halves2bfloat162(l2,l3);
}

// ---------------- seg mean (f32 msgs) + base + relu -> split out ----------------
template<int WIDTH>
__global__ void seg_relu_split_kernel(const float* __restrict__ Q, const float* __restrict__ Base,
                                      const int* __restrict__ off, const int* __restrict__ nbr,
                                      bf16* __restrict__ Ch, bf16* __restrict__ Cl)
{
    int row = blockIdx.x;
    int t = threadIdx.x;
    int s = off[row], e = off[row + 1];
    float4 acc = make_float4(0.f,0.f,0.f,0.f);
    for (int i = s; i < e; i++){
        int nb = __ldg(&nbr[i]);
        float4 v = __ldg((const float4*)(Q + (size_t)nb*WIDTH) + t);
        acc.x += v.x; acc.y += v.y; acc.z += v.z; acc.w += v.w;
    }
    float inv = (e > s) ? 1.0f/(float)(e - s) : 0.0f;
    float4 b = __ldg((const float4*)(Base + (size_t)row*WIDTH) + t);
    float x0 = fmaxf(b.x + acc.x*inv, 0.f);
    float x1 = fmaxf(b.y + acc.y*inv, 0.f);
    float x2 = fmaxf(b.z + acc.z*inv, 0.f);
    float x3 = fmaxf(b.w + acc.w*inv, 0.f);
    bf16 h0=__float2bfloat16(x0), h1=__float2bfloat16(x1);
    bf16 h2=__float2bfloat16(x2), h3=__float2bfloat16(x3);
    bf16 l0=__float2bfloat16(x0-__bfloat162float(h0));
    bf16 l1=__float2bfloat16(x1-__bfloat162float(h1));
    bf16 l2=__float2bfloat16(x2-__bfloat162float(h2));
    bf16 l3=__float2bfloat16(x3-__bfloat162float(h3));
    bf162* och = (bf162*)(Ch + (size_t)row*WIDTH);
    bf162* ocl = (bf162*)(Cl + (size_t)row*WIDTH);
    och[2*t]   = __halves2bfloat162(h0,h1);
    och[2*t+1] = __halves2bfloat162(h2,h3);
    ocl[2*t]   = __halves2bfloat162(l0,l1);
    ocl[2*t+1] = __halves2bfloat162(l2,l3);
}

// ---------------- segment mean: f32-in, accumulate into f32 out ----------------
template <int WIDTH>
__global__ void seg_mean_acc_kernel(const float* __restrict__ X, const int* __restrict__ off,
                                    const int* __restrict__ nbr, float* __restrict__ C)
{
    int row = blockIdx.x;
    int t = threadIdx.x;
    int s = off[row], e = off[row + 1];
    float4 acc = make_float4(0.f, 0.f, 0.f, 0.f);
    for (int i = s; i < e; i++) {
        int nb = __ldg(&nbr[i]);
        float4 v = __ldg((const float4*)(X + (size_t)nb * WIDTH) + t);
        acc.x += v.x; acc.y += v.y; acc.z += v.z; acc.w += v.w;
    }
    float inv = (e > s) ? 1.0f / (float)(e - s) : 0.0f;
    float4* cp = (float4*)(C + (size_t)row * WIDTH) + t;
    float4 o = *cp;
    o.x += acc.x*inv; o.y += acc.y*inv; o.z += acc.z*inv; o.w += acc.w*inv;
    *cp = o;
}

// ---------------- host orchestration ----------------
#define SYM(p, s) cudaGetSymbolAddress((void**)&(p), s)

static inline GemmDesc mk_desc(
    const bf16* A1h, const bf16* A1l, const bf16* B1h, const bf16* B1l, int K1,
    const bf16* A2h, const bf16* A2l, const bf16* B2h, const bf16* B2l, int K2,
    int M, int N, const float* bias, const float* Demb, const int* idx,
    float* C, bf16* Ch, bf16* Cl, int flags)
{
    GemmDesc d;
    d.A1h=A1h; d.A1l=A1l; d.B1h=B1h; d.B1l=B1l; d.K1=K1;
    d.A2h=A2h; d.A2l=A2l; d.B2h=B2h; d.B2l=B2l; d.K2=K2;
    d.M=M; d.N=N; d.bias=bias; d.Demb=Demb; d.idx=idx;
    d.C=C; d.Ch=Ch; d.Cl=Cl; d.flags=flags;
    d.start=0; d.tx=N/128;
    return d;
}

static inline void launch_batch(GemmDesc* descs, int n, cudaStream_t st)
{
    GemmBatch gb;
    int total = 0;
    for (int i = 0; i < n; i++){
        descs[i].start = total;
        total += descs[i].tx * ((descs[i].M + 127)/128);
        gb.g[i] = descs[i];
    }
    for (int i = n; i < 3; i++){ gb.g[i] = descs[n-1]; gb.g[i].start = 0x7FFFFFFF; }
    gb.n = n;
    mma_gemm_batched<<<total, 256, GEMM_SMEM_BYTES, st>>>(gb);
}

// static aux resources (created on first, uncaptured, call)
struct Aux {
    cudaStream_t s2;
    cudaEvent_t ev[4];
    Aux(){
        cudaStreamCreateWithFlags(&s2, cudaStreamNonBlocking);
        for (int i = 0; i < 4; i++)
            cudaEventCreateWithFlags(&ev[i], cudaEventDisableTiming);
    }
};

extern "C" void kernel_launch(void* const* d_in, const int* in_sizes, int n_in,
                              void* d_out, int out_size)
{
    static Aux aux;

    // pick the stream that is actually being captured (or per-thread default otherwise)
    cudaStream_t ms = cudaStreamPerThread;
    {
        cudaStreamCaptureStatus st = cudaStreamCaptureStatusNone;
        if (cudaStreamIsCapturing(cudaStreamPerThread, &st) == cudaSuccess &&
            st == cudaStreamCaptureStatusActive) {
            ms = cudaStreamPerThread;
        } else {
            cudaGetLastError();
            st = cudaStreamCaptureStatusNone;
            if (cudaStreamIsCapturing(cudaStreamLegacy, &st) == cudaSuccess &&
                st == cudaStreamCaptureStatusActive) {
                ms = cudaStreamLegacy;
            }
            cudaGetLastError();
        }
    }
    cudaStream_t s2 = aux.s2;

    const float* mf   = (const float*)d_in[0];
    const float* df   = (const float*)d_in[1];
    const int*   mid  = (const int*)d_in[2];
    const int*   did  = (const int*)d_in[3];
    const int*   esrc = (const int*)d_in[4];
    const int*   edst = (const int*)d_in[5];
    const float* Wm   = (const float*)d_in[6];
    const float* bm   = (const float*)d_in[7];
    const float* Wd   = (const float*)d_in[8];
    const float* bd   = (const float*)d_in[9];
    const float* memb = (const float*)d_in[10];
    const float* demb = (const float*)d_in[11];
    const float* W1mdl = (const float*)d_in[12];
    const float* b1md  = (const float*)d_in[13];
    const float* W1mdr = (const float*)d_in[14];
    const float* W1dml = (const float*)d_in[15];
    const float* b1dm  = (const float*)d_in[16];
    const float* W1dmr = (const float*)d_in[17];
    const float* W2mdl = (const float*)d_in[18];
    const float* b2md  = (const float*)d_in[19];
    const float* W2mdr = (const float*)d_in[20];
    const float* W2dml = (const float*)d_in[21];
    const float* b2dm  = (const float*)d_in[22];
    const float* W2dmr = (const float*)d_in[23];

    float* out = (float*)d_out;
    float* o_m = out;
    float* o_d = out + (size_t)NM * OD;

    bf16 *mfh,*mfl,*dfh,*dfl,*xmh,*xml,*xdh,*xdl,*adh,*adl,*adh2,*adl2,*hmh,*hml,*hdh,*hdl;
    bf16 *wmh,*wml,*wdh,*wdl;
    bf16 *w1mdlh,*w1mdll,*w1mdrh,*w1mdrl,*w1dmlh,*w1dmll,*w1dmrh,*w1dmrl;
    bf16 *w2mdlh,*w2mdll,*w2mdrh,*w2mdrl,*w2dmlh,*w2dmll,*w2dmrh,*w2dmrl;
    float *qd,*basem,*ud;
    int *cnt_m,*cnt_d,*off_m,*off_d,*cur_m,*cur_d,*csr_src,*csr_dst;
    SYM(mfh,g_mfh); SYM(mfl,g_mfl); SYM(dfh,g_dfh); SYM(dfl,g_dfl);
    SYM(xmh,g_xmh); SYM(xml,g_xml); SYM(xdh,g_xdh); SYM(xdl,g_xdl);
    SYM(adh,g_adh); SYM(adl,g_adl); SYM(adh2,g_adh2); SYM(adl2,g_adl2);
    SYM(hmh,g_hmh); SYM(hml,g_hml); SYM(hdh,g_hdh); SYM(hdl,g_hdl);
    SYM(wmh,g_wmh); SYM(wml,g_wml); SYM(wdh,g_wdh); SYM(wdl,g_wdl);
    SYM(w1mdlh,g_w1mdlh); SYM(w1mdll,g_w1mdll); SYM(w1mdrh,g_w1mdrh); SYM(w1mdrl,g_w1mdrl);
    SYM(w1dmlh,g_w1dmlh); SYM(w1dmll,g_w1dmll); SYM(w1dmrh,g_w1dmrh); SYM(w1dmrl,g_w1dmrl);
    SYM(w2mdlh,g_w2mdlh); SYM(w2mdll,g_w2mdll); SYM(w2mdrh,g_w2mdrh); SYM(w2mdrl,g_w2mdrl);
    SYM(w2dmlh,g_w2dmlh); SYM(w2dmll,g_w2dmll); SYM(w2dmrh,g_w2dmrh); SYM(w2dmrl,g_w2dmrl);
    SYM(qd,g_qd); SYM(basem,g_base); SYM(ud,g_ud);
    SYM(cnt_m,g_cnt_m); SYM(cnt_d,g_cnt_d); SYM(off_m,g_off_m); SYM(off_d,g_off_d);
    SYM(cur_m,g_cur_m); SYM(cur_d,g_cur_d); SYM(csr_src,g_csr_src); SYM(csr_dst,g_csr_dst);

    cudaFuncSetAttribute(mma_gemm_batched, cudaFuncAttributeMaxDynamicSharedMemorySize, GEMM_SMEM_BYTES);

    // ---- fork s2: CSR chain (latency-bound, tiny grids) overlaps with splits+encoders ----
    cudaEventRecord(aux.ev[0], ms);
    cudaStreamWaitEvent(s2, aux.ev[0], 0);
    zero_kernel<<<(NM + 255)/256, 256, 0, s2>>>(cnt_m, NM, cnt_d, ND);
    count_edges_kernel<<<(NE + 255) / 256, 256, 0, s2>>>(esrc, edst, cnt_m, cnt_d, NE);
    exscan2_kernel<<<2, 1024, 0, s2>>>(cnt_d, off_d, cur_d, ND, cnt_m, off_m, cur_m, NM);
    fill_csr_kernel<<<(NE + 255) / 256, 256, 0, s2>>>(esrc, edst, cur_m, cur_d, csr_src, csr_dst, NE);
    cudaEventRecord(aux.ev[1], s2);   // CSR ready

    // ---- main: splits ----
    {
        SplitSet s1;
        s1.x[0]=mf; s1.h[0]=mfh; s1.l[0]=mfl; s1.n4[0]=NM*FIN/4;
        s1.x[1]=df; s1.h[1]=dfh; s1.l[1]=dfl; s1.n4[1]=ND*FIN/4;
        s1.x[2]=Wm; s1.h[2]=wmh; s1.l[2]=wml; s1.n4[2]=FIN*HD/4;
        s1.x[3]=Wd; s1.h[3]=wdh; s1.l[3]=wdl; s1.n4[3]=FIN*HD/4;
        int mx = NM*FIN/4;
        bsplit_kernel<<<dim3((mx + 255)/256, 4), 256, 0, ms>>>(s1);

        SplitSet s2s;
        s2s.x[0]=W1mdl; s2s.h[0]=w1mdlh; s2s.l[0]=w1mdll; s2s.n4[0]=HD*H1/4;
        s2s.x[1]=W1mdr; s2s.h[1]=w1mdrh; s2s.l[1]=w1mdrl; s2s.n4[1]=HD*H1/4;
        s2s.x[2]=W1dml; s2s.h[2]=w1dmlh; s2s.l[2]=w1dmll; s2s.n4[2]=HD*H1/4;
        s2s.x[3]=W1dmr; s2s.h[3]=w1dmrh; s2s.l[3]=w1dmrl; s2s.n4[3]=HD*H1/4;
        bsplit_kernel<<<dim3((HD*H1/4 + 255)/256, 4), 256, 0, ms>>>(s2s);

        SplitSet s3;
        s3.x[0]=W2mdl; s3.h[0]=w2mdlh; s3.l[0]=w2mdll; s3.n4[0]=H1*OD/4;
        s3.x[1]=W2mdr; s3.h[1]=w2mdrh; s3.l[1]=w2mdrl; s3.n4[1]=H1*OD/4;
        s3.x[2]=W2dml; s3.h[2]=w2dmlh; s3.l[2]=w2dmll; s3.n4[2]=H1*OD/4;
        s3.x[3]=W2dmr; s3.h[3]=w2dmrh; s3.l[3]=w2dmrl; s3.n4[3]=H1*OD/4;
        bsplit_kernel<<<dim3((H1*OD/4 + 255)/256, 4), 256, 0, ms>>>(s3);
    }

    // ---- main: L1 encoders (no CSR dependency) ----
    {
        GemmDesc ds[2] = {
            mk_desc(mfh, mfl, wmh, wml, FIN, 0,0,0,0, 0,
                    NM, HD, bm, memb, mid, nullptr, xmh, xml, F_BIAS|F_GATH|F_SPLIT),
            mk_desc(dfh, dfl, wdh, wdl, FIN, 0,0,0,0, 0,
                    ND, HD, bd, demb, did, nullptr, xdh, xdl, F_BIAS|F_GATH|F_SPLIT)
        };
        launch_batch(ds, 2, ms);
    }

    // join: CSR must be ready before first gather
    cudaStreamWaitEvent(ms, aux.ev[1], 0);

    // ---- main: layer1 md aggregation ----
    seg_mean_split_kernel<HD><<<ND, HD/4, 0, ms>>>(xmh, xml, off_d, csr_src, adh, adl);

    // ---- main: Group B: L1md-dual + qd + base_m ----
    {
        GemmDesc ds[3] = {
            mk_desc(adh, adl, w1mdlh, w1mdll, HD, xdh, xdl, w1mdrh, w1mdrl, HD,
                    ND, H1, b1md, nullptr, nullptr, nullptr, hdh, hdl, F_BIAS|F_RELU|F_SPLIT),
            mk_desc(xdh, xdl, w1dmlh, w1dmll, HD, 0,0,0,0, 0,
                    ND, H1, nullptr, nullptr, nullptr, qd, nullptr, nullptr, 0),
            mk_desc(xmh, xml, w1dmrh, w1dmrl, HD, 0,0,0,0, 0,
                    NM, H1, b1dm, nullptr, nullptr, basem, nullptr, nullptr, F_BIAS)
        };
        launch_batch(ds, 3, ms);
    }

    // ---- main: h_m = relu(base + mean(q_d)); layer2 md aggregation ----
    seg_relu_split_kernel<H1><<<NM, H1/4, 0, ms>>>(qd, basem, off_m, csr_dst, hmh, hml);
    seg_mean_split_kernel<H1><<<ND, H1/4, 0, ms>>>(hmh, hml, off_d, csr_src, adh2, adl2);

    // ---- main: Group C: L2md-dual + ud + o_m base ----
    {
        GemmDesc ds[3] = {
            mk_desc(adh2, adl2, w2mdlh, w2mdll, H1, hdh, hdl, w2mdrh, w2mdrl, H1,
                    ND, OD, b2md, nullptr, nullptr, o_d, nullptr, nullptr, F_BIAS),
            mk_desc(hdh, hdl, w2dmlh, w2dmll, H1, 0,0,0,0, 0,
                    ND, OD, nullptr, nullptr, nullptr, ud, nullptr, nullptr, 0),
            mk_desc(hmh, hml, w2dmrh, w2dmrl, H1, 0,0,0,0, 0,
                    NM, OD, b2dm, nullptr, nullptr, o_m, nullptr, nullptr, F_BIAS)
        };
        launch_batch(ds, 3, ms);
    }

    // ---- main: o_m += mean(ud over incident diseases) ----
    seg_mean_acc_kernel<OD><<<NM, OD/4, 0, ms>>>(ud, off_m, csr_dst, o_m);
}

// round 11
// speedup vs baseline: 1.4668x; 1.1775x over previous
#include <cuda_runtime.h>
#include <cuda_fp16.h>
#include <cstdint>

#define NM 20000
#define ND 8000
#define NE 200000
#define FIN 384
#define HD 512
#define H1 512
#define OD 256

typedef __half  h16;
typedef __half2 h162;

// ---------------- scratch (device globals) ----------------
__device__ h16 g_mfh[NM*FIN], g_mfl[NM*FIN];
__device__ h16 g_dfh[ND*FIN], g_dfl[ND*FIN];
__device__ h16 g_xmh[NM*HD],  g_xml[NM*HD];
__device__ h16 g_xdh[ND*HD],  g_xdl[ND*HD];
__device__ h16 g_adh[ND*HD],  g_adl[ND*HD];    // layer1 agg onto disease
__device__ h16 g_adh2[ND*H1], g_adl2[ND*H1];   // layer2 agg onto disease
__device__ h16 g_hmh[NM*H1],  g_hml[NM*H1];
__device__ h16 g_hdh[ND*H1],  g_hdl[ND*H1];
__device__ float g_qd[ND*H1];
__device__ float g_base[NM*H1];
__device__ float g_ud[ND*OD];
// weights: single fp16 (B operand)
__device__ h16 g_wm[FIN*HD], g_wd[FIN*HD];
__device__ h16 g_w1mdl[HD*H1], g_w1mdr[HD*H1];
__device__ h16 g_w1dml[HD*H1], g_w1dmr[HD*H1];
__device__ h16 g_w2mdl[H1*OD], g_w2mdr[H1*OD];
__device__ h16 g_w2dml[H1*OD], g_w2dmr[H1*OD];
__device__ int g_cnt_m[NM], g_cnt_d[ND];
__device__ int g_off_m[NM+1], g_off_d[ND+1];
__device__ int g_cur_m[NM], g_cur_d[ND];
__device__ int g_csr_src[NE];
__device__ int g_csr_dst[NE];

// ---------------- PTX helpers ----------------
__device__ __forceinline__ void ldsm_x4(uint32_t& r0,uint32_t& r1,uint32_t& r2,uint32_t& r3,uint32_t a){
    asm volatile("ldmatrix.sync.aligned.m8n8.x4.shared.b16 {%0,%1,%2,%3},[%4];"
                 :"=r"(r0),"=r"(r1),"=r"(r2),"=r"(r3):"r"(a));
}
__device__ __forceinline__ void ldsm_x4t(uint32_t& r0,uint32_t& r1,uint32_t& r2,uint32_t& r3,uint32_t a){
    asm volatile("ldmatrix.sync.aligned.m8n8.x4.trans.shared.b16 {%0,%1,%2,%3},[%4];"
                 :"=r"(r0),"=r"(r1),"=r"(r2),"=r"(r3):"r"(a));
}
__device__ __forceinline__ void mma_f16(float* c, const uint32_t* a, uint32_t b0, uint32_t b1){
    asm volatile("mma.sync.aligned.m16n8k16.row.col.f32.f16.f16.f32 "
        "{%0,%1,%2,%3},{%4,%5,%6,%7},{%8,%9},{%0,%1,%2,%3};"
        :"+f"(c[0]),"+f"(c[1]),"+f"(c[2]),"+f"(c[3])
        :"r"(a[0]),"r"(a[1]),"r"(a[2]),"r"(a[3]),"r"(b0),"r"(b1));
}
__device__ __forceinline__ void cpa16(uint32_t d, const void* s, bool p){
    int sz = p ? 16 : 0;
    asm volatile("cp.async.cg.shared.global [%0],[%1],16,%2;"::"r"(d),"l"(s),"r"(sz));
}
__device__ __forceinline__ void split_h(float x, h16& h, h16& l){
    h = __float2half_rn(x);
    l = __float2half_rn(x - __half2float(h));
}

// smem geometry (fp16 elements)
#define SA 40
#define SB 136
#define ASZ (128*SA)                 // 5120
#define BSZ (32*SB)                  // 4352
#define STAGE_E (2*ASZ + BSZ)        // 14592
#define GEMM_SMEM_BYTES (2*STAGE_E*2) // 58368

// flags
#define F_BIAS  1
#define F_RELU  2
#define F_GATH  4
#define F_SPLIT 8

struct GemmDesc {
    const h16 *A1h,*A1l,*B1;
    const h16 *A2h,*A2l,*B2;
    int K1, K2, M, N;
    const float *bias, *Demb; const int* idx;
    float* C; h16 *Ch, *Cl;
    int flags;
    int start, tx;
};
struct GemmBatch { GemmDesc g[3]; int n; };

// ---------------- batched fp16x2 tensor-core GEMM ----------------
// C = (A1h+A1l)@B1 (+ (A2h+A2l)@B2); B pre-rounded to fp16
__global__ __launch_bounds__(256,2) void mma_gemm_batched(GemmBatch gb)
{
    extern __shared__ h16 smem[];
    uint32_t sbase = (uint32_t)__cvta_generic_to_shared(smem);
    const int tid  = threadIdx.x;
    const int lane = tid & 31;
    const int wid  = tid >> 5;
    const int wm   = (wid & 3) * 32;
    const int wn   = (wid >> 2) * 64;

    int gi = 0;
    if (gb.n > 1 && (int)blockIdx.x >= gb.g[1].start) gi = 1;
    if (gb.n > 2 && (int)blockIdx.x >= gb.g[2].start) gi = 2;
    const GemmDesc d = gb.g[gi];

    const int rel = blockIdx.x - d.start;
    const int bn  = (rel % d.tx) * 128;
    const int bm  = (rel / d.tx) * 128;
    const int M = d.M, N = d.N;
    const int S1 = d.K1 >> 5, S2 = d.K2 >> 5, S = S1 + S2;

    float acc[2][8][4];
#pragma unroll
    for (int i=0;i<2;i++)
#pragma unroll
        for (int j=0;j<8;j++)
#pragma unroll
            for (int k=0;k<4;k++) acc[i][j][k] = 0.f;

    auto prefetch = [&](int s){
        const h16 *Ah,*Al,*B; int K,k0;
        if (s < S1){ Ah=d.A1h; Al=d.A1l; B=d.B1; K=d.K1; k0=s<<5; }
        else       { Ah=d.A2h; Al=d.A2l; B=d.B2; K=d.K2; k0=(s-S1)<<5; }
        uint32_t sb = sbase + (uint32_t)((s&1)*STAGE_E*2);
        int ar = tid>>2, ac = (tid&3)*8;
#pragma unroll
        for (int i=0;i<2;i++){
            int row = bm + ar + 64*i;
            bool ok = row < M;
            int sr = ok ? row : 0;
            uint32_t dd = sb + (uint32_t)(((ar+64*i)*SA + ac)*2);
            cpa16(dd,          Ah + (size_t)sr*K + k0 + ac, ok);
            cpa16(dd + ASZ*2,  Al + (size_t)sr*K + k0 + ac, ok);
        }
        int bk = tid>>4, bc = (tid&15)*8;
#pragma unroll
        for (int i=0;i<2;i++){
            int k = bk + 16*i;
            uint32_t dd = sb + (uint32_t)(((2*ASZ) + k*SB + bc)*2);
            cpa16(dd, B + (size_t)(k0 + k)*N + bn + bc, true);
        }
        asm volatile("cp.async.commit_group;");
    };

    prefetch(0);
    for (int s=0;s<S;s++){
        if (s+1 < S){
            prefetch(s+1);
            asm volatile("cp.async.wait_group 1;");
        } else {
            asm volatile("cp.async.wait_group 0;");
        }
        __syncthreads();
        uint32_t sb = sbase + (uint32_t)((s&1)*STAGE_E*2);
#pragma unroll
        for (int kk=0;kk<2;kk++){
            const int k16 = kk*16;
            const int loff = (lane>>1)&8;
            uint32_t ah[2][4], al[2][4];
#pragma unroll
            for (int mf=0;mf<2;mf++){
                uint32_t a = sb + (uint32_t)((((wm + mf*16 + (lane&15))*SA) + k16 + loff)*2);
                ldsm_x4(ah[mf][0],ah[mf][1],ah[mf][2],ah[mf][3], a);
                ldsm_x4(al[mf][0],al[mf][1],al[mf][2],al[mf][3], a + ASZ*2);
            }
#pragma unroll
            for (int nb=0;nb<4;nb++){
                uint32_t a = sb + (uint32_t)(((2*ASZ) + (k16 + (lane&15))*SB + wn + nb*16 + loff)*2);
                uint32_t bh[4];
                ldsm_x4t(bh[0],bh[1],bh[2],bh[3], a);
#pragma unroll
                for (int h=0;h<2;h++){
#pragma unroll
                    for (int mf=0;mf<2;mf++){
                        float* c = acc[mf][nb*2+h];
                        mma_f16(c, ah[mf], bh[2*h], bh[2*h+1]);
                        mma_f16(c, al[mf], bh[2*h], bh[2*h+1]);
                    }
                }
            }
        }
        __syncthreads();
    }

    const int fl = d.flags;
#pragma unroll
    for (int mf=0;mf<2;mf++){
#pragma unroll
        for (int nf=0;nf<8;nf++){
            int col = bn + wn + nf*8 + (lane&3)*2;
#pragma unroll
            for (int half=0;half<2;half++){
                int row = bm + wm + mf*16 + (lane>>2) + half*8;
                if (row >= M) continue;
                float v0 = acc[mf][nf][half*2+0];
                float v1 = acc[mf][nf][half*2+1];
                if (fl & F_BIAS){ v0 += __ldg(&d.bias[col]); v1 += __ldg(&d.bias[col+1]); }
                if (fl & F_GATH){
                    int g = __ldg(&d.idx[row]);
                    const float* e = d.Demb + (size_t)g*N + col;
                    v0 += __ldg(&e[0]); v1 += __ldg(&e[1]);
                }
                if (fl & F_RELU){ v0 = fmaxf(v0,0.f); v1 = fmaxf(v1,0.f); }
                if (fl & F_SPLIT){
                    h16 h0,l0,h1,l1;
                    split_h(v0,h0,l0); split_h(v1,h1,l1);
                    *(h162*)(d.Ch + (size_t)row*N + col) = __halves2half2(h0,h1);
                    *(h162*)(d.Cl + (size_t)row*N + col) = __halves2half2(l0,l1);
                } else {
                    float2 o; o.x=v0; o.y=v1;
                    *(float2*)(d.C + (size_t)row*N + col) = o;
                }
            }
        }
    }
}

// ---------------- batched split fp32 -> fp16 hi(/lo) ----------------
struct SplitSet { const float* x[4]; h16* h[4]; h16* l[4]; int n4[4]; };
__global__ void bsplit_kernel(SplitSet ss)
{
    int z = blockIdx.y;
    const float* X = ss.x[z]; h16* H = ss.h[z]; h16* L = ss.l[z];
    int n4 = ss.n4[z];
    int i = blockIdx.x*blockDim.x + threadIdx.x;
    if (i < n4){
        float4 v = ((const float4*)X)[i];
        h16 h0,h1,h2,h3,l0,l1,l2,l3;
        split_h(v.x,h0,l0); split_h(v.y,h1,l1);
        split_h(v.z,h2,l2); split_h(v.w,h3,l3);
        ((h162*)H)[2*i]   = __halves2half2(h0,h1);
        ((h162*)H)[2*i+1] = __halves2half2(h2,h3);
        if (L){
            ((h162*)L)[2*i]   = __halves2half2(l0,l1);
            ((h162*)L)[2*i+1] = __halves2half2(l2,l3);
        }
    }
}

// ---------------- CSR build ----------------
__global__ void zero_kernel(int* a, int na, int* b, int nb)
{
    int i = blockIdx.x*blockDim.x + threadIdx.x;
    if (i < na) a[i] = 0;
    if (i < nb) b[i] = 0;
}

__global__ void count_edges_kernel(const int* __restrict__ src, const int* __restrict__ dst,
                                   int* __restrict__ cm, int* __restrict__ cd, int E)
{
    int i = blockIdx.x * blockDim.x + threadIdx.x;
    if (i < E) {
        atomicAdd(&cd[dst[i]], 1);
        atomicAdd(&cm[src[i]], 1);
    }
}

__global__ void exscan2_kernel(const int* __restrict__ cnt_d, int* __restrict__ off_d, int* __restrict__ cur_d, int n_d,
                               const int* __restrict__ cnt_m, int* __restrict__ off_m, int* __restrict__ cur_m, int n_m)
{
    const int* cnt; int* off; int* cur; int n;
    if (blockIdx.x == 0){ cnt = cnt_d; off = off_d; cur = cur_d; n = n_d; }
    else               { cnt = cnt_m; off = off_m; cur = cur_m; n = n_m; }
    __shared__ int wsum[32];
    int t = threadIdx.x;
    int chunk = (n + 1023) >> 10;
    int s = t * chunk; if (s > n) s = n;
    int e = s + chunk; if (e > n) e = n;
    int sum = 0;
    for (int i = s; i < e; i++) sum += cnt[i];
    int lane = t & 31, w = t >> 5;
    int v = sum;
#pragma unroll
    for (int dd = 1; dd < 32; dd <<= 1){
        int o = __shfl_up_sync(0xFFFFFFFFu, v, dd);
        if (lane >= dd) v += o;
    }
    if (lane == 31) wsum[w] = v;
    __syncthreads();
    if (w == 0){
        int x = wsum[lane];
#pragma unroll
        for (int dd = 1; dd < 32; dd <<= 1){
            int o = __shfl_up_sync(0xFFFFFFFFu, x, dd);
            if (lane >= dd) x += o;
        }
        wsum[lane] = x;
    }
    __syncthreads();
    int run = v - sum + (w > 0 ? wsum[w-1] : 0);
    for (int i = s; i < e; i++){
        off[i] = run; cur[i] = run; run += cnt[i];
    }
    if (t == 1023) off[n] = run;
}

__global__ void fill_csr_kernel(const int* __restrict__ src, const int* __restrict__ dst,
                                int* __restrict__ cur_m, int* __restrict__ cur_d,
                                int* __restrict__ csr_src, int* __restrict__ csr_dst, int E)
{
    int i = blockIdx.x * blockDim.x + threadIdx.x;
    if (i < E) {
        int m = src[i], d = dst[i];
        int p = atomicAdd(&cur_d[d], 1);
        csr_src[p] = m;
        int q = atomicAdd(&cur_m[m], 1);
        csr_dst[q] = d;
    }
}

// ---------------- segment mean: split-in -> split-out ----------------
template<int WIDTH>
__global__ void seg_mean_split_kernel(const h16* __restrict__ Xh, const h16* __restrict__ Xl,
                                      const int* __restrict__ off, const int* __restrict__ nbr,
                                      h16* __restrict__ Ch, h16* __restrict__ Cl)
{
    int row = blockIdx.x;
    int t = threadIdx.x;
    int s = off[row], e = off[row + 1];
    float a0=0.f,a1=0.f,a2=0.f,a3=0.f;
    for (int i = s; i < e; i++){
        int nb = __ldg(&nbr[i]);
        const h162* ph = (const h162*)(Xh + (size_t)nb*WIDTH);
        const h162* pl = (const h162*)(Xl + (size_t)nb*WIDTH);
        float2 h0 = __half22float2(__ldg(&ph[2*t]));
        float2 h1 = __half22float2(__ldg(&ph[2*t+1]));
        float2 l0 = __half22float2(__ldg(&pl[2*t]));
        float2 l1 = __half22float2(__ldg(&pl[2*t+1]));
        a0 += h0.x + l0.x; a1 += h0.y + l0.y;
        a2 += h1.x + l1.x; a3 += h1.y + l1.y;
    }
    float inv = (e > s) ? 1.0f/(float)(e - s) : 0.0f;
    a0 *= inv; a1 *= inv; a2 *= inv; a3 *= inv;
    h16 h0,h1,h2,h3,l0,l1,l2,l3;
    split_h(a0,h0,l0); split_h(a1,h1,l1);
    split_h(a2,h2,l2); split_h(a3,h3,l3);
    h162* och = (h162*)(Ch + (size_t)row*WIDTH);
    h162* ocl = (h162*)(Cl + (size_t)row*WIDTH);
    och[2*t]   = __halves2half2(h0,h1);
    och[2*t+1] = __halves2half2(h2,h3);
    ocl[2*t]   = __halves2half2(l0,l1);
    ocl[2*t+1] = __halves2half2(l2,l3);
}

// ---------------- seg mean (f32 msgs) + base + relu -> split out ----------------
template<int WIDTH>
__global__ void seg_relu_split_kernel(const float* __restrict__ Q, const float* __restrict__ Base,
                                      const int* __restrict__ off, const int* __restrict__ nbr,
                                      h16* __restrict__ Ch, h16* __restrict__ Cl)
{
    int row = blockIdx.x;
    int t = threadIdx.x;
    int s = off[row], e = off[row + 1];
    float4 acc = make_float4(0.f,0.f,0.f,0.f);
    for (int i = s; i < e; i++){
        int nb = __ldg(&nbr[i]);
        float4 v = __ldg((const float4*)(Q + (size_t)nb*WIDTH) + t);
        acc.x += v.x; acc.y += v.y; acc.z += v.z; acc.w += v.w;
    }
    float inv = (e > s) ? 1.0f/(float)(e - s) : 0.0f;
    float4 b = __ldg((const float4*)(Base + (size_t)row*WIDTH) + t);
    float x0 = fmaxf(b.x + acc.x*inv, 0.f);
    float x1 = fmaxf(b.y + acc.y*inv, 0.f);
    float x2 = fmaxf(b.z + acc.z*inv, 0.f);
    float x3 = fmaxf(b.w + acc.w*inv, 0.f);
    h16 h0,h1,h2,h3,l0,l1,l2,l3;
    split_h(x0,h0,l0); split_h(x1,h1,l1);
    split_h(x2,h2,l2); split_h(x3,h3,l3);
    h162* och = (h162*)(Ch + (size_t)row*WIDTH);
    h162* ocl = (h162*)(Cl + (size_t)row*WIDTH);
    och[2*t]   = __halves2half2(h0,h1);
    och[2*t+1] = __halves2half2(h2,h3);
    ocl[2*t]   = __halves2half2(l0,l1);
    ocl[2*t+1] = __halves2half2(l2,l3);
}

// ---------------- segment mean: f32-in, accumulate into f32 out ----------------
template <int WIDTH>
__global__ void seg_mean_acc_kernel(const float* __restrict__ X, const int* __restrict__ off,
                                    const int* __restrict__ nbr, float* __restrict__ C)
{
    int row = blockIdx.x;
    int t = threadIdx.x;
    int s = off[row], e = off[row + 1];
    float4 acc = make_float4(0.f, 0.f, 0.f, 0.f);
    for (int i = s; i < e; i++) {
        int nb = __ldg(&nbr[i]);
        float4 v = __ldg((const float4*)(X + (size_t)nb * WIDTH) + t);
        acc.x += v.x; acc.y += v.y; acc.z += v.z; acc.w += v.w;
    }
    float inv = (e > s) ? 1.0f / (float)(e - s) : 0.0f;
    float4* cp = (float4*)(C + (size_t)row * WIDTH) + t;
    float4 o = *cp;
    o.x += acc.x*inv; o.y += acc.y*inv; o.z += acc.z*inv; o.w += acc.w*inv;
    *cp = o;
}

// ---------------- host orchestration ----------------
#define SYM(p, s) cudaGetSymbolAddress((void**)&(p), s)

static inline GemmDesc mk_desc(
    const h16* A1h, const h16* A1l, const h16* B1, int K1,
    const h16* A2h, const h16* A2l, const h16* B2, int K2,
    int M, int N, const float* bias, const float* Demb, const int* idx,
    float* C, h16* Ch, h16* Cl, int flags)
{
    GemmDesc d;
    d.A1h=A1h; d.A1l=A1l; d.B1=B1; d.K1=K1;
    d.A2h=A2h; d.A2l=A2l; d.B2=B2; d.K2=K2;
    d.M=M; d.N=N; d.bias=bias; d.Demb=Demb; d.idx=idx;
    d.C=C; d.Ch=Ch; d.Cl=Cl; d.flags=flags;
    d.start=0; d.tx=N/128;
    return d;
}

static inline void launch_batch(GemmDesc* descs, int n, cudaStream_t st)
{
    GemmBatch gb;
    int total = 0;
    for (int i = 0; i < n; i++){
        descs[i].start = total;
        total += descs[i].tx * ((descs[i].M + 127)/128);
        gb.g[i] = descs[i];
    }
    for (int i = n; i < 3; i++){ gb.g[i] = descs[n-1]; gb.g[i].start = 0x7FFFFFFF; }
    gb.n = n;
    mma_gemm_batched<<<total, 256, GEMM_SMEM_BYTES, st>>>(gb);
}

// static aux resources (created on first, uncaptured, call)
struct Aux {
    cudaStream_t s2;
    cudaEvent_t ev[4];
    Aux(){
        cudaStreamCreateWithFlags(&s2, cudaStreamNonBlocking);
        for (int i = 0; i < 4; i++)
            cudaEventCreateWithFlags(&ev[i], cudaEventDisableTiming);
    }
};

extern "C" void kernel_launch(void* const* d_in, const int* in_sizes, int n_in,
                              void* d_out, int out_size)
{
    static Aux aux;

    cudaStream_t ms = cudaStreamPerThread;
    {
        cudaStreamCaptureStatus st = cudaStreamCaptureStatusNone;
        if (cudaStreamIsCapturing(cudaStreamPerThread, &st) == cudaSuccess &&
            st == cudaStreamCaptureStatusActive) {
            ms = cudaStreamPerThread;
        } else {
            cudaGetLastError();
            st = cudaStreamCaptureStatusNone;
            if (cudaStreamIsCapturing(cudaStreamLegacy, &st) == cudaSuccess &&
                st == cudaStreamCaptureStatusActive) {
                ms = cudaStreamLegacy;
            }
            cudaGetLastError();
        }
    }
    cudaStream_t s2 = aux.s2;

    const float* mf   = (const float*)d_in[0];
    const float* df   = (const float*)d_in[1];
    const int*   mid  = (const int*)d_in[2];
    const int*   did  = (const int*)d_in[3];
    const int*   esrc = (const int*)d_in[4];
    const int*   edst = (const int*)d_in[5];
    const float* Wm   = (const float*)d_in[6];
    const float* bm   = (const float*)d_in[7];
    const float* Wd   = (const float*)d_in[8];
    const float* bd   = (const float*)d_in[9];
    const float* memb = (const float*)d_in[10];
    const float* demb = (const float*)d_in[11];
    const float* W1mdl = (const float*)d_in[12];
    const float* b1md  = (const float*)d_in[13];
    const float* W1mdr = (const float*)d_in[14];
    const float* W1dml = (const float*)d_in[15];
    const float* b1dm  = (const float*)d_in[16];
    const float* W1dmr = (const float*)d_in[17];
    const float* W2mdl = (const float*)d_in[18];
    const float* b2md  = (const float*)d_in[19];
    const float* W2mdr = (const float*)d_in[20];
    const float* W2dml = (const float*)d_in[21];
    const float* b2dm  = (const float*)d_in[22];
    const float* W2dmr = (const float*)d_in[23];

    float* out = (float*)d_out;
    float* o_m = out;
    float* o_d = out + (size_t)NM * OD;

    h16 *mfh,*mfl,*dfh,*dfl,*xmh,*xml,*xdh,*xdl,*adh,*adl,*adh2,*adl2,*hmh,*hml,*hdh,*hdl;
    h16 *wm,*wd,*w1mdl,*w1mdr,*w1dml,*w1dmr,*w2mdl,*w2mdr,*w2dml,*w2dmr;
    float *qd,*basem,*ud;
    int *cnt_m,*cnt_d,*off_m,*off_d,*cur_m,*cur_d,*csr_src,*csr_dst;
    SYM(mfh,g_mfh); SYM(mfl,g_mfl); SYM(dfh,g_dfh); SYM(dfl,g_dfl);
    SYM(xmh,g_xmh); SYM(xml,g_xml); SYM(xdh,g_xdh); SYM(xdl,g_xdl);
    SYM(adh,g_adh); SYM(adl,g_adl); SYM(adh2,g_adh2); SYM(adl2,g_adl2);
    SYM(hmh,g_hmh); SYM(hml,g_hml); SYM(hdh,g_hdh); SYM(hdl,g_hdl);
    SYM(wm,g_wm); SYM(wd,g_wd);
    SYM(w1mdl,g_w1mdl); SYM(w1mdr,g_w1mdr); SYM(w1dml,g_w1dml); SYM(w1dmr,g_w1dmr);
    SYM(w2mdl,g_w2mdl); SYM(w2mdr,g_w2mdr); SYM(w2dml,g_w2dml); SYM(w2dmr,g_w2dmr);
    SYM(qd,g_qd); SYM(basem,g_base); SYM(ud,g_ud);
    SYM(cnt_m,g_cnt_m); SYM(cnt_d,g_cnt_d); SYM(off_m,g_off_m); SYM(off_d,g_off_d);
    SYM(cur_m,g_cur_m); SYM(cur_d,g_cur_d); SYM(csr_src,g_csr_src); SYM(csr_dst,g_csr_dst);

    cudaFuncSetAttribute(mma_gemm_batched, cudaFuncAttributeMaxDynamicSharedMemorySize, GEMM_SMEM_BYTES);

    // ---- fork s2: CSR chain overlaps with splits+encoders ----
    cudaEventRecord(aux.ev[0], ms);
    cudaStreamWaitEvent(s2, aux.ev[0], 0);
    zero_kernel<<<(NM + 255)/256, 256, 0, s2>>>(cnt_m, NM, cnt_d, ND);
    count_edges_kernel<<<(NE + 255) / 256, 256, 0, s2>>>(esrc, edst, cnt_m, cnt_d, NE);
    exscan2_kernel<<<2, 1024, 0, s2>>>(cnt_d, off_d, cur_d, ND, cnt_m, off_m, cur_m, NM);
    fill_csr_kernel<<<(NE + 255) / 256, 256, 0, s2>>>(esrc, edst, cur_m, cur_d, csr_src, csr_dst, NE);
    cudaEventRecord(aux.ev[1], s2);   // CSR ready

    // ---- main: splits ----
    {
        SplitSet s1;
        s1.x[0]=mf; s1.h[0]=mfh; s1.l[0]=mfl; s1.n4[0]=NM*FIN/4;
        s1.x[1]=df; s1.h[1]=dfh; s1.l[1]=dfl; s1.n4[1]=ND*FIN/4;
        s1.x[2]=Wm; s1.h[2]=wm;  s1.l[2]=nullptr; s1.n4[2]=FIN*HD/4;
        s1.x[3]=Wd; s1.h[3]=wd;  s1.l[3]=nullptr; s1.n4[3]=FIN*HD/4;
        int mx = NM*FIN/4;
        bsplit_kernel<<<dim3((mx + 255)/256, 4), 256, 0, ms>>>(s1);

        SplitSet s2s;
        s2s.x[0]=W1mdl; s2s.h[0]=w1mdl; s2s.l[0]=nullptr; s2s.n4[0]=HD*H1/4;
        s2s.x[1]=W1mdr; s2s.h[1]=w1mdr; s2s.l[1]=nullptr; s2s.n4[1]=HD*H1/4;
        s2s.x[2]=W1dml; s2s.h[2]=w1dml; s2s.l[2]=nullptr; s2s.n4[2]=HD*H1/4;
        s2s.x[3]=W1dmr; s2s.h[3]=w1dmr; s2s.l[3]=nullptr; s2s.n4[3]=HD*H1/4;
        bsplit_kernel<<<dim3((HD*H1/4 + 255)/256, 4), 256, 0, ms>>>(s2s);

        SplitSet s3;
        s3.x[0]=W2mdl; s3.h[0]=w2mdl; s3.l[0]=nullptr; s3.n4[0]=H1*OD/4;
        s3.x[1]=W2mdr; s3.h[1]=w2mdr; s3.l[1]=nullptr; s3.n4[1]=H1*OD/4;
        s3.x[2]=W2dml; s3.h[2]=w2dml; s3.l[2]=nullptr; s3.n4[2]=H1*OD/4;
        s3.x[3]=W2dmr; s3.h[3]=w2dmr; s3.l[3]=nullptr; s3.n4[3]=H1*OD/4;
        bsplit_kernel<<<dim3((H1*OD/4 + 255)/256, 4), 256, 0, ms>>>(s3);
    }

    // ---- main: L1 encoders ----
    {
        GemmDesc ds[2] = {
            mk_desc(mfh, mfl, wm, FIN, 0,0,0, 0,
                    NM, HD, bm, memb, mid, nullptr, xmh, xml, F_BIAS|F_GATH|F_SPLIT),
            mk_desc(dfh, dfl, wd, FIN, 0,0,0, 0,
                    ND, HD, bd, demb, did, nullptr, xdh, xdl, F_BIAS|F_GATH|F_SPLIT)
        };
        launch_batch(ds, 2, ms);
    }

    // join: CSR must be ready before first gather
    cudaStreamWaitEvent(ms, aux.ev[1], 0);

    // ---- main: layer1 md aggregation ----
    seg_mean_split_kernel<HD><<<ND, HD/4, 0, ms>>>(xmh, xml, off_d, csr_src, adh, adl);

    // ---- main: Group B: L1md-dual + qd + base_m ----
    {
        GemmDesc ds[3] = {
            mk_desc(adh, adl, w1mdl, HD, xdh, xdl, w1mdr, HD,
                    ND, H1, b1md, nullptr, nullptr, nullptr, hdh, hdl, F_BIAS|F_RELU|F_SPLIT),
            mk_desc(xdh, xdl, w1dml, HD, 0,0,0, 0,
                    ND, H1, nullptr, nullptr, nullptr, qd, nullptr, nullptr, 0),
            mk_desc(xmh, xml, w1dmr, HD, 0,0,0, 0,
                    NM, H1, b1dm, nullptr, nullptr, basem, nullptr, nullptr, F_BIAS)
        };
        launch_batch(ds, 3, ms);
    }

    // ---- main: h_m = relu(base + mean(q_d)); layer2 md aggregation ----
    seg_relu_split_kernel<H1><<<NM, H1/4, 0, ms>>>(qd, basem, off_m, csr_dst, hmh, hml);
    seg_mean_split_kernel<H1><<<ND, H1/4, 0, ms>>>(hmh, hml, off_d, csr_src, adh2, adl2);

    // ---- main: Group C: L2md-dual + ud + o_m base ----
    {
        GemmDesc ds[3] = {
            mk_desc(adh2, adl2, w2mdl, H1, hdh, hdl, w2mdr, H1,
                    ND, OD, b2md, nullptr, nullptr, o_d, nullptr, nullptr, F_BIAS),
            mk_desc(hdh, hdl, w2dml, H1, 0,0,0, 0,
                    ND, OD, nullptr, nullptr, nullptr, ud, nullptr, nullptr, 0),
            mk_desc(hmh, hml, w2dmr, H1, 0,0,0, 0,
                    NM, OD, b2dm, nullptr, nullptr, o_m, nullptr, nullptr, F_BIAS)
        };
        launch_batch(ds, 3, ms);
    }

    // ---- main: o_m += mean(ud over incident diseases) ----
    seg_mean_acc_kernel<OD><<<NM, OD/4, 0, ms>>>(ud, off_m, csr_dst, o_m);
}

// round 12
// speedup vs baseline: 2.0947x; 1.4280x over previous
#include <cuda_runtime.h>
#include <cuda_fp16.h>
#include <cstdint>

#define NM 20000
#define ND 8000
#define NE 200000
#define FIN 384
#define HD 512
#define H1 512
#define OD 256

typedef __half  h16;
typedef __half2 h162;

// ---------------- scratch (device globals) ----------------
__device__ h16 g_mf[NM*FIN];
__device__ h16 g_df[ND*FIN];
__device__ h16 g_xm[NM*HD];
__device__ h16 g_xd[ND*HD];
__device__ h16 g_ad[ND*HD];     // layer1 agg onto disease
__device__ h16 g_ad2[ND*H1];    // layer2 agg onto disease
__device__ h16 g_hm[NM*H1];
__device__ h16 g_hd[ND*H1];
__device__ float g_qd[ND*H1];
__device__ float g_base[NM*H1];
__device__ float g_ud[ND*OD];
__device__ h16 g_wm[FIN*HD], g_wd[FIN*HD];
__device__ h16 g_w1mdl[HD*H1], g_w1mdr[HD*H1];
__device__ h16 g_w1dml[HD*H1], g_w1dmr[HD*H1];
__device__ h16 g_w2mdl[H1*OD], g_w2mdr[H1*OD];
__device__ h16 g_w2dml[H1*OD], g_w2dmr[H1*OD];
__device__ int g_cnt_m[NM], g_cnt_d[ND];
__device__ int g_off_m[NM+1], g_off_d[ND+1];
__device__ int g_cur_m[NM], g_cur_d[ND];
__device__ int g_csr_src[NE];
__device__ int g_csr_dst[NE];

// ---------------- PTX helpers ----------------
__device__ __forceinline__ void ldsm_x4(uint32_t& r0,uint32_t& r1,uint32_t& r2,uint32_t& r3,uint32_t a){
    asm volatile("ldmatrix.sync.aligned.m8n8.x4.shared.b16 {%0,%1,%2,%3},[%4];"
                 :"=r"(r0),"=r"(r1),"=r"(r2),"=r"(r3):"r"(a));
}
__device__ __forceinline__ void ldsm_x4t(uint32_t& r0,uint32_t& r1,uint32_t& r2,uint32_t& r3,uint32_t a){
    asm volatile("ldmatrix.sync.aligned.m8n8.x4.trans.shared.b16 {%0,%1,%2,%3},[%4];"
                 :"=r"(r0),"=r"(r1),"=r"(r2),"=r"(r3):"r"(a));
}
__device__ __forceinline__ void mma_f16(float* c, const uint32_t* a, uint32_t b0, uint32_t b1){
    asm volatile("mma.sync.aligned.m16n8k16.row.col.f32.f16.f16.f32 "
        "{%0,%1,%2,%3},{%4,%5,%6,%7},{%8,%9},{%0,%1,%2,%3};"
        :"+f"(c[0]),"+f"(c[1]),"+f"(c[2]),"+f"(c[3])
        :"r"(a[0]),"r"(a[1]),"r"(a[2]),"r"(a[3]),"r"(b0),"r"(b1));
}
__device__ __forceinline__ void cpa16(uint32_t d, const void* s, bool p){
    int sz = p ? 16 : 0;
    asm volatile("cp.async.cg.shared.global [%0],[%1],16,%2;"::"r"(d),"l"(s),"r"(sz));
}

// smem geometry (fp16 elements)
#define SA 40
#define SB 136
#define ASZ (128*SA)                 // 5120
#define BSZ (32*SB)                  // 4352
#define STAGE_E (ASZ + BSZ)          // 9472
#define GEMM_SMEM_BYTES (2*STAGE_E*2) // 37888

// flags
#define F_BIAS  1
#define F_RELU  2
#define F_GATH  4
#define F_HALF  8

struct GemmDesc {
    const h16 *A1,*B1;
    const h16 *A2,*B2;
    int K1, K2, M, N;
    const float *bias, *Demb; const int* idx;
    float* C; h16 *Ch;
    int flags;
    int start, tx;
};
struct GemmBatch { GemmDesc g[3]; int n; };

// ---------------- batched fp16 tensor-core GEMM ----------------
__global__ __launch_bounds__(256,2) void mma_gemm_batched(GemmBatch gb)
{
    extern __shared__ h16 smem[];
    uint32_t sbase = (uint32_t)__cvta_generic_to_shared(smem);
    const int tid  = threadIdx.x;
    const int lane = tid & 31;
    const int wid  = tid >> 5;
    const int wm   = (wid & 3) * 32;
    const int wn   = (wid >> 2) * 64;

    int gi = 0;
    if (gb.n > 1 && (int)blockIdx.x >= gb.g[1].start) gi = 1;
    if (gb.n > 2 && (int)blockIdx.x >= gb.g[2].start) gi = 2;
    const GemmDesc d = gb.g[gi];

    const int rel = blockIdx.x - d.start;
    const int bn  = (rel % d.tx) * 128;
    const int bm  = (rel / d.tx) * 128;
    const int M = d.M, N = d.N;
    const int S1 = d.K1 >> 5, S2 = d.K2 >> 5, S = S1 + S2;

    float acc[2][8][4];
#pragma unroll
    for (int i=0;i<2;i++)
#pragma unroll
        for (int j=0;j<8;j++)
#pragma unroll
            for (int k=0;k<4;k++) acc[i][j][k] = 0.f;

    auto prefetch = [&](int s){
        const h16 *A,*B; int K,k0;
        if (s < S1){ A=d.A1; B=d.B1; K=d.K1; k0=s<<5; }
        else       { A=d.A2; B=d.B2; K=d.K2; k0=(s-S1)<<5; }
        uint32_t sb = sbase + (uint32_t)((s&1)*STAGE_E*2);
        int ar = tid>>2, ac = (tid&3)*8;
#pragma unroll
        for (int i=0;i<2;i++){
            int row = bm + ar + 64*i;
            bool ok = row < M;
            int sr = ok ? row : 0;
            uint32_t dd = sb + (uint32_t)(((ar+64*i)*SA + ac)*2);
            cpa16(dd, A + (size_t)sr*K + k0 + ac, ok);
        }
        int bk = tid>>4, bc = (tid&15)*8;
#pragma unroll
        for (int i=0;i<2;i++){
            int k = bk + 16*i;
            uint32_t dd = sb + (uint32_t)((ASZ + k*SB + bc)*2);
            cpa16(dd, B + (size_t)(k0 + k)*N + bn + bc, true);
        }
        asm volatile("cp.async.commit_group;");
    };

    prefetch(0);
    for (int s=0;s<S;s++){
        if (s+1 < S){
            prefetch(s+1);
            asm volatile("cp.async.wait_group 1;");
        } else {
            asm volatile("cp.async.wait_group 0;");
        }
        __syncthreads();
        uint32_t sb = sbase + (uint32_t)((s&1)*STAGE_E*2);
#pragma unroll
        for (int kk=0;kk<2;kk++){
            const int k16 = kk*16;
            const int loff = (lane>>1)&8;
            uint32_t ah[2][4];
#pragma unroll
            for (int mf=0;mf<2;mf++){
                uint32_t a = sb + (uint32_t)((((wm + mf*16 + (lane&15))*SA) + k16 + loff)*2);
                ldsm_x4(ah[mf][0],ah[mf][1],ah[mf][2],ah[mf][3], a);
            }
#pragma unroll
            for (int nb=0;nb<4;nb++){
                uint32_t a = sb + (uint32_t)((ASZ + (k16 + (lane&15))*SB + wn + nb*16 + loff)*2);
                uint32_t bh[4];
                ldsm_x4t(bh[0],bh[1],bh[2],bh[3], a);
#pragma unroll
                for (int h=0;h<2;h++){
#pragma unroll
                    for (int mf=0;mf<2;mf++){
                        mma_f16(acc[mf][nb*2+h], ah[mf], bh[2*h], bh[2*h+1]);
                    }
                }
            }
        }
        __syncthreads();
    }

    const int fl = d.flags;
#pragma unroll
    for (int mf=0;mf<2;mf++){
#pragma unroll
        for (int nf=0;nf<8;nf++){
            int col = bn + wn + nf*8 + (lane&3)*2;
#pragma unroll
            for (int half=0;half<2;half++){
                int row = bm + wm + mf*16 + (lane>>2) + half*8;
                if (row >= M) continue;
                float v0 = acc[mf][nf][half*2+0];
                float v1 = acc[mf][nf][half*2+1];
                if (fl & F_BIAS){ v0 += __ldg(&d.bias[col]); v1 += __ldg(&d.bias[col+1]); }
                if (fl & F_GATH){
                    int g = __ldg(&d.idx[row]);
                    const float* e = d.Demb + (size_t)g*N + col;
                    v0 += __ldg(&e[0]); v1 += __ldg(&e[1]);
                }
                if (fl & F_RELU){ v0 = fmaxf(v0,0.f); v1 = fmaxf(v1,0.f); }
                if (fl & F_HALF){
                    *(h162*)(d.Ch + (size_t)row*N + col) =
                        __halves2half2(__float2half_rn(v0), __float2half_rn(v1));
                } else {
                    float2 o; o.x=v0; o.y=v1;
                    *(float2*)(d.C + (size_t)row*N + col) = o;
                }
            }
        }
    }
}

// ---------------- batched convert fp32 -> fp16 ----------------
struct SplitSet { const float* x[4]; h16* h[4]; int n4[4]; };
__global__ void bsplit_kernel(SplitSet ss)
{
    int z = blockIdx.y;
    const float* X = ss.x[z]; h16* H = ss.h[z];
    int n4 = ss.n4[z];
    int i = blockIdx.x*blockDim.x + threadIdx.x;
    if (i < n4){
        float4 v = ((const float4*)X)[i];
        ((h162*)H)[2*i]   = __halves2half2(__float2half_rn(v.x), __float2half_rn(v.y));
        ((h162*)H)[2*i+1] = __halves2half2(__float2half_rn(v.z), __float2half_rn(v.w));
    }
}

// ---------------- CSR build ----------------
__global__ void zero_kernel(int* a, int na, int* b, int nb)
{
    int i = blockIdx.x*blockDim.x + threadIdx.x;
    if (i < na) a[i] = 0;
    if (i < nb) b[i] = 0;
}

__global__ void count_edges_kernel(const int* __restrict__ src, const int* __restrict__ dst,
                                   int* __restrict__ cm, int* __restrict__ cd, int E)
{
    int i = blockIdx.x * blockDim.x + threadIdx.x;
    if (i < E) {
        atomicAdd(&cd[dst[i]], 1);
        atomicAdd(&cm[src[i]], 1);
    }
}

__global__ void exscan2_kernel(const int* __restrict__ cnt_d, int* __restrict__ off_d, int* __restrict__ cur_d, int n_d,
                               const int* __restrict__ cnt_m, int* __restrict__ off_m, int* __restrict__ cur_m, int n_m)
{
    const int* cnt; int* off; int* cur; int n;
    if (blockIdx.x == 0){ cnt = cnt_d; off = off_d; cur = cur_d; n = n_d; }
    else               { cnt = cnt_m; off = off_m; cur = cur_m; n = n_m; }
    __shared__ int wsum[32];
    int t = threadIdx.x;
    int chunk = (n + 1023) >> 10;
    int s = t * chunk; if (s > n) s = n;
    int e = s + chunk; if (e > n) e = n;
    int sum = 0;
    for (int i = s; i < e; i++) sum += cnt[i];
    int lane = t & 31, w = t >> 5;
    int v = sum;
#pragma unroll
    for (int dd = 1; dd < 32; dd <<= 1){
        int o = __shfl_up_sync(0xFFFFFFFFu, v, dd);
        if (lane >= dd) v += o;
    }
    if (lane == 31) wsum[w] = v;
    __syncthreads();
    if (w == 0){
        int x = wsum[lane];
#pragma unroll
        for (int dd = 1; dd < 32; dd <<= 1){
            int o = __shfl_up_sync(0xFFFFFFFFu, x, dd);
            if (lane >= dd) x += o;
        }
        wsum[lane] = x;
    }
    __syncthreads();
    int run = v - sum + (w > 0 ? wsum[w-1] : 0);
    for (int i = s; i < e; i++){
        off[i] = run; cur[i] = run; run += cnt[i];
    }
    if (t == 1023) off[n] = run;
}

__global__ void fill_csr_kernel(const int* __restrict__ src, const int* __restrict__ dst,
                                int* __restrict__ cur_m, int* __restrict__ cur_d,
                                int* __restrict__ csr_src, int* __restrict__ csr_dst, int E)
{
    int i = blockIdx.x * blockDim.x + threadIdx.x;
    if (i < E) {
        int m = src[i], d = dst[i];
        int p = atomicAdd(&cur_d[d], 1);
        csr_src[p] = m;
        int q = atomicAdd(&cur_m[m], 1);
        csr_dst[q] = d;
    }
}

// ---------------- segment mean: fp16-in -> fp16-out ----------------
template<int WIDTH>
__global__ void seg_mean_kernel(const h16* __restrict__ X,
                                const int* __restrict__ off, const int* __restrict__ nbr,
                                h16* __restrict__ C)
{
    int row = blockIdx.x;
    int t = threadIdx.x;  // WIDTH/4 threads
    int s = off[row], e = off[row + 1];
    float a0=0.f,a1=0.f,a2=0.f,a3=0.f;
    for (int i = s; i < e; i++){
        int nb = __ldg(&nbr[i]);
        const h162* ph = (const h162*)(X + (size_t)nb*WIDTH);
        float2 h0 = __half22float2(__ldg(&ph[2*t]));
        float2 h1 = __half22float2(__ldg(&ph[2*t+1]));
        a0 += h0.x; a1 += h0.y; a2 += h1.x; a3 += h1.y;
    }
    float inv = (e > s) ? 1.0f/(float)(e - s) : 0.0f;
    a0 *= inv; a1 *= inv; a2 *= inv; a3 *= inv;
    h162* oc = (h162*)(C + (size_t)row*WIDTH);
    oc[2*t]   = __halves2half2(__float2half_rn(a0), __float2half_rn(a1));
    oc[2*t+1] = __halves2half2(__float2half_rn(a2), __float2half_rn(a3));
}

// ---------------- seg mean (f32 msgs) + base + relu -> fp16 out ----------------
template<int WIDTH>
__global__ void seg_relu_kernel(const float* __restrict__ Q, const float* __restrict__ Base,
                                const int* __restrict__ off, const int* __restrict__ nbr,
                                h16* __restrict__ C)
{
    int row = blockIdx.x;
    int t = threadIdx.x;
    int s = off[row], e = off[row + 1];
    float4 acc = make_float4(0.f,0.f,0.f,0.f);
    for (int i = s; i < e; i++){
        int nb = __ldg(&nbr[i]);
        float4 v = __ldg((const float4*)(Q + (size_t)nb*WIDTH) + t);
        acc.x += v.x; acc.y += v.y; acc.z += v.z; acc.w += v.w;
    }
    float inv = (e > s) ? 1.0f/(float)(e - s) : 0.0f;
    float4 b = __ldg((const float4*)(Base + (size_t)row*WIDTH) + t);
    float x0 = fmaxf(b.x + acc.x*inv, 0.f);
    float x1 = fmaxf(b.y + acc.y*inv, 0.f);
    float x2 = fmaxf(b.z + acc.z*inv, 0.f);
    float x3 = fmaxf(b.w + acc.w*inv, 0.f);
    h162* oc = (h162*)(C + (size_t)row*WIDTH);
    oc[2*t]   = __halves2half2(__float2half_rn(x0), __float2half_rn(x1));
    oc[2*t+1] = __halves2half2(__float2half_rn(x2), __float2half_rn(x3));
}

// ---------------- segment mean: f32-in, accumulate into f32 out ----------------
template <int WIDTH>
__global__ void seg_mean_acc_kernel(const float* __restrict__ X, const int* __restrict__ off,
                                    const int* __restrict__ nbr, float* __restrict__ C)
{
    int row = blockIdx.x;
    int t = threadIdx.x;
    int s = off[row], e = off[row + 1];
    float4 acc = make_float4(0.f, 0.f, 0.f, 0.f);
    for (int i = s; i < e; i++) {
        int nb = __ldg(&nbr[i]);
        float4 v = __ldg((const float4*)(X + (size_t)nb * WIDTH) + t);
        acc.x += v.x; acc.y += v.y; acc.z += v.z; acc.w += v.w;
    }
    float inv = (e > s) ? 1.0f / (float)(e - s) : 0.0f;
    float4* cp = (float4*)(C + (size_t)row * WIDTH) + t;
    float4 o = *cp;
    o.x += acc.x*inv; o.y += acc.y*inv; o.z += acc.z*inv; o.w += acc.w*inv;
    *cp = o;
}

// ---------------- host orchestration ----------------
#define SYM(p, s) cudaGetSymbolAddress((void**)&(p), s)

static inline GemmDesc mk_desc(
    const h16* A1, const h16* B1, int K1,
    const h16* A2, const h16* B2, int K2,
    int M, int N, const float* bias, const float* Demb, const int* idx,
    float* C, h16* Ch, int flags)
{
    GemmDesc d;
    d.A1=A1; d.B1=B1; d.K1=K1;
    d.A2=A2; d.B2=B2; d.K2=K2;
    d.M=M; d.N=N; d.bias=bias; d.Demb=Demb; d.idx=idx;
    d.C=C; d.Ch=Ch; d.flags=flags;
    d.start=0; d.tx=N/128;
    return d;
}

static inline void launch_batch(GemmDesc* descs, int n, cudaStream_t st)
{
    GemmBatch gb;
    int total = 0;
    for (int i = 0; i < n; i++){
        descs[i].start = total;
        total += descs[i].tx * ((descs[i].M + 127)/128);
        gb.g[i] = descs[i];
    }
    for (int i = n; i < 3; i++){ gb.g[i] = descs[n-1]; gb.g[i].start = 0x7FFFFFFF; }
    gb.n = n;
    mma_gemm_batched<<<total, 256, GEMM_SMEM_BYTES, st>>>(gb);
}

// static aux resources (created on first, uncaptured, call)
struct Aux {
    cudaStream_t s2;
    cudaEvent_t ev[4];
    Aux(){
        cudaStreamCreateWithFlags(&s2, cudaStreamNonBlocking);
        for (int i = 0; i < 4; i++)
            cudaEventCreateWithFlags(&ev[i], cudaEventDisableTiming);
    }
};

extern "C" void kernel_launch(void* const* d_in, const int* in_sizes, int n_in,
                              void* d_out, int out_size)
{
    static Aux aux;

    cudaStream_t ms = cudaStreamPerThread;
    {
        cudaStreamCaptureStatus st = cudaStreamCaptureStatusNone;
        if (cudaStreamIsCapturing(cudaStreamPerThread, &st) == cudaSuccess &&
            st == cudaStreamCaptureStatusActive) {
            ms = cudaStreamPerThread;
        } else {
            cudaGetLastError();
            st = cudaStreamCaptureStatusNone;
            if (cudaStreamIsCapturing(cudaStreamLegacy, &st) == cudaSuccess &&
                st == cudaStreamCaptureStatusActive) {
                ms = cudaStreamLegacy;
            }
            cudaGetLastError();
        }
    }
    cudaStream_t s2 = aux.s2;

    const float* mf   = (const float*)d_in[0];
    const float* df   = (const float*)d_in[1];
    const int*   mid  = (const int*)d_in[2];
    const int*   did  = (const int*)d_in[3];
    const int*   esrc = (const int*)d_in[4];
    const int*   edst = (const int*)d_in[5];
    const float* Wm   = (const float*)d_in[6];
    const float* bm   = (const float*)d_in[7];
    const float* Wd   = (const float*)d_in[8];
    const float* bd   = (const float*)d_in[9];
    const float* memb = (const float*)d_in[10];
    const float* demb = (const float*)d_in[11];
    const float* W1mdl = (const float*)d_in[12];
    const float* b1md  = (const float*)d_in[13];
    const float* W1mdr = (const float*)d_in[14];
    const float* W1dml = (const float*)d_in[15];
    const float* b1dm  = (const float*)d_in[16];
    const float* W1dmr = (const float*)d_in[17];
    const float* W2mdl = (const float*)d_in[18];
    const float* b2md  = (const float*)d_in[19];
    const float* W2mdr = (const float*)d_in[20];
    const float* W2dml = (const float*)d_in[21];
    const float* b2dm  = (const float*)d_in[22];
    const float* W2dmr = (const float*)d_in[23];

    float* out = (float*)d_out;
    float* o_m = out;
    float* o_d = out + (size_t)NM * OD;

    h16 *mfh,*dfh,*xm,*xd,*ad,*ad2,*hm,*hd;
    h16 *wm,*wd,*w1mdl,*w1mdr,*w1dml,*w1dmr,*w2mdl,*w2mdr,*w2dml,*w2dmr;
    float *qd,*basem,*ud;
    int *cnt_m,*cnt_d,*off_m,*off_d,*cur_m,*cur_d,*csr_src,*csr_dst;
    SYM(mfh,g_mf); SYM(dfh,g_df);
    SYM(xm,g_xm); SYM(xd,g_xd);
    SYM(ad,g_ad); SYM(ad2,g_ad2);
    SYM(hm,g_hm); SYM(hd,g_hd);
    SYM(wm,g_wm); SYM(wd,g_wd);
    SYM(w1mdl,g_w1mdl); SYM(w1mdr,g_w1mdr); SYM(w1dml,g_w1dml); SYM(w1dmr,g_w1dmr);
    SYM(w2mdl,g_w2mdl); SYM(w2mdr,g_w2mdr); SYM(w2dml,g_w2dml); SYM(w2dmr,g_w2dmr);
    SYM(qd,g_qd); SYM(basem,g_base); SYM(ud,g_ud);
    SYM(cnt_m,g_cnt_m); SYM(cnt_d,g_cnt_d); SYM(off_m,g_off_m); SYM(off_d,g_off_d);
    SYM(cur_m,g_cur_m); SYM(cur_d,g_cur_d); SYM(csr_src,g_csr_src); SYM(csr_dst,g_csr_dst);

    cudaFuncSetAttribute(mma_gemm_batched, cudaFuncAttributeMaxDynamicSharedMemorySize, GEMM_SMEM_BYTES);

    // ---- fork s2: CSR chain overlaps with splits+encoders ----
    cudaEventRecord(aux.ev[0], ms);
    cudaStreamWaitEvent(s2, aux.ev[0], 0);
    zero_kernel<<<(NM + 255)/256, 256, 0, s2>>>(cnt_m, NM, cnt_d, ND);
    count_edges_kernel<<<(NE + 255) / 256, 256, 0, s2>>>(esrc, edst, cnt_m, cnt_d, NE);
    exscan2_kernel<<<2, 1024, 0, s2>>>(cnt_d, off_d, cur_d, ND, cnt_m, off_m, cur_m, NM);
    fill_csr_kernel<<<(NE + 255) / 256, 256, 0, s2>>>(esrc, edst, cur_m, cur_d, csr_src, csr_dst, NE);
    cudaEventRecord(aux.ev[1], s2);   // CSR ready

    // ---- main: converts ----
    {
        SplitSet s1;
        s1.x[0]=mf; s1.h[0]=mfh; s1.n4[0]=NM*FIN/4;
        s1.x[1]=df; s1.h[1]=dfh; s1.n4[1]=ND*FIN/4;
        s1.x[2]=Wm; s1.h[2]=wm;  s1.n4[2]=FIN*HD/4;
        s1.x[3]=Wd; s1.h[3]=wd;  s1.n4[3]=FIN*HD/4;
        int mx = NM*FIN/4;
        bsplit_kernel<<<dim3((mx + 255)/256, 4), 256, 0, ms>>>(s1);

        SplitSet s2s;
        s2s.x[0]=W1mdl; s2s.h[0]=w1mdl; s2s.n4[0]=HD*H1/4;
        s2s.x[1]=W1mdr; s2s.h[1]=w1mdr; s2s.n4[1]=HD*H1/4;
        s2s.x[2]=W1dml; s2s.h[2]=w1dml; s2s.n4[2]=HD*H1/4;
        s2s.x[3]=W1dmr; s2s.h[3]=w1dmr; s2s.n4[3]=HD*H1/4;
        bsplit_kernel<<<dim3((HD*H1/4 + 255)/256, 4), 256, 0, ms>>>(s2s);

        SplitSet s3;
        s3.x[0]=W2mdl; s3.h[0]=w2mdl; s3.n4[0]=H1*OD/4;
        s3.x[1]=W2mdr; s3.h[1]=w2mdr; s3.n4[1]=H1*OD/4;
        s3.x[2]=W2dml; s3.h[2]=w2dml; s3.n4[2]=H1*OD/4;
        s3.x[3]=W2dmr; s3.h[3]=w2dmr; s3.n4[3]=H1*OD/4;
        bsplit_kernel<<<dim3((H1*OD/4 + 255)/256, 4), 256, 0, ms>>>(s3);
    }

    // ---- main: L1 encoders ----
    {
        GemmDesc ds[2] = {
            mk_desc(mfh, wm, FIN, 0,0, 0,
                    NM, HD, bm, memb, mid, nullptr, xm, F_BIAS|F_GATH|F_HALF),
            mk_desc(dfh, wd, FIN, 0,0, 0,
                    ND, HD, bd, demb, did, nullptr, xd, F_BIAS|F_GATH|F_HALF)
        };
        launch_batch(ds, 2, ms);
    }

    // join: CSR must be ready before first gather
    cudaStreamWaitEvent(ms, aux.ev[1], 0);

    // ---- main: layer1 md aggregation ----
    seg_mean_kernel<HD><<<ND, HD/4, 0, ms>>>(xm, off_d, csr_src, ad);

    // ---- main: Group B: L1md-dual + qd + base_m ----
    {
        GemmDesc ds[3] = {
            mk_desc(ad, w1mdl, HD, xd, w1mdr, HD,
                    ND, H1, b1md, nullptr, nullptr, nullptr, hd, F_BIAS|F_RELU|F_HALF),
            mk_desc(xd, w1dml, HD, 0,0, 0,
                    ND, H1, nullptr, nullptr, nullptr, qd, nullptr, 0),
            mk_desc(xm, w1dmr, HD, 0,0, 0,
                    NM, H1, b1dm, nullptr, nullptr, basem, nullptr, F_BIAS)
        };
        launch_batch(ds, 3, ms);
    }

    // ---- main: h_m = relu(base + mean(q_d)); layer2 md aggregation ----
    seg_relu_kernel<H1><<<NM, H1/4, 0, ms>>>(qd, basem, off_m, csr_dst, hm);
    seg_mean_kernel<H1><<<ND, H1/4, 0, ms>>>(hm, off_d, csr_src, ad2);

    // ---- main: Group C: L2md-dual + ud + o_m base ----
    {
        GemmDesc ds[3] = {
            mk_desc(ad2, w2mdl, H1, hd, w2mdr, H1,
                    ND, OD, b2md, nullptr, nullptr, o_d, nullptr, F_BIAS),
            mk_desc(hd, w2dml, H1, 0,0, 0,
                    ND, OD, nullptr, nullptr, nullptr, ud, nullptr, 0),
            mk_desc(hm, w2dmr, H1, 0,0, 0,
                    NM, OD, b2dm, nullptr, nullptr, o_m, nullptr, F_BIAS)
        };
        launch_batch(ds, 3, ms);
    }

    // ---- main: o_m += mean(ud over incident diseases) ----
    seg_mean_acc_kernel<OD><<<NM, OD/4, 0, ms>>>(ud, off_m, csr_dst, o_m);
}

// round 13
// speedup vs baseline: 2.6323x; 1.2567x over previous
#include <cuda_runtime.h>
#include <cuda_fp16.h>
#include <cstdint>

#define NM 20000
#define ND 8000
#define NE 200000
#define FIN 384
#define HD 512
#define H1 512
#define OD 256

typedef __half  h16;
typedef __half2 h162;

// ---------------- scratch (device globals) ----------------
__device__ h16 g_mf[NM*FIN];
__device__ h16 g_df[ND*FIN];
__device__ h16 g_xm[NM*HD];
__device__ h16 g_xd[ND*HD];
__device__ h16 g_ad[ND*HD];     // layer1 agg onto disease
__device__ h16 g_ad2[ND*H1];    // layer2 agg onto disease
__device__ h16 g_hm[NM*H1];
__device__ h16 g_hd[ND*H1];
__device__ h16 g_qd[ND*H1];     // layer1 dm projected messages (fp16)
__device__ float g_base[NM*H1]; // layer1 dm base (f32: dominant term, keep precise)
__device__ h16 g_ud[ND*OD];     // layer2 dm projected messages (fp16)
__device__ h16 g_wm[FIN*HD], g_wd[FIN*HD];
__device__ h16 g_w1mdl[HD*H1], g_w1mdr[HD*H1];
__device__ h16 g_w1dml[HD*H1], g_w1dmr[HD*H1];
__device__ h16 g_w2mdl[H1*OD], g_w2mdr[H1*OD];
__device__ h16 g_w2dml[H1*OD], g_w2dmr[H1*OD];
__device__ int g_cnt_m[NM], g_cnt_d[ND];
__device__ int g_off_m[NM+1], g_off_d[ND+1];
__device__ int g_cur_m[NM], g_cur_d[ND];
__device__ int g_csr_src[NE];
__device__ int g_csr_dst[NE];

// ---------------- PTX helpers ----------------
__device__ __forceinline__ void ldsm_x4(uint32_t& r0,uint32_t& r1,uint32_t& r2,uint32_t& r3,uint32_t a){
    asm volatile("ldmatrix.sync.aligned.m8n8.x4.shared.b16 {%0,%1,%2,%3},[%4];"
                 :"=r"(r0),"=r"(r1),"=r"(r2),"=r"(r3):"r"(a));
}
__device__ __forceinline__ void ldsm_x4t(uint32_t& r0,uint32_t& r1,uint32_t& r2,uint32_t& r3,uint32_t a){
    asm volatile("ldmatrix.sync.aligned.m8n8.x4.trans.shared.b16 {%0,%1,%2,%3},[%4];"
                 :"=r"(r0),"=r"(r1),"=r"(r2),"=r"(r3):"r"(a));
}
__device__ __forceinline__ void mma_f16(float* c, const uint32_t* a, uint32_t b0, uint32_t b1){
    asm volatile("mma.sync.aligned.m16n8k16.row.col.f32.f16.f16.f32 "
        "{%0,%1,%2,%3},{%4,%5,%6,%7},{%8,%9},{%0,%1,%2,%3};"
        :"+f"(c[0]),"+f"(c[1]),"+f"(c[2]),"+f"(c[3])
        :"r"(a[0]),"r"(a[1]),"r"(a[2]),"r"(a[3]),"r"(b0),"r"(b1));
}
__device__ __forceinline__ void cpa16(uint32_t d, const void* s, bool p){
    int sz = p ? 16 : 0;
    asm volatile("cp.async.cg.shared.global [%0],[%1],16,%2;"::"r"(d),"l"(s),"r"(sz));
}

// smem geometry (fp16 elements)
#define SA 40
#define SB 136
#define ASZ (128*SA)                 // 5120
#define BSZ (32*SB)                  // 4352
#define STAGE_E (ASZ + BSZ)          // 9472
#define GEMM_SMEM_BYTES (2*STAGE_E*2) // 37888

// flags
#define F_BIAS  1
#define F_RELU  2
#define F_GATH  4
#define F_HALF  8

struct GemmDesc {
    const h16 *A1,*B1;
    const h16 *A2,*B2;
    int K1, K2, M, N;
    const float *bias, *Demb; const int* idx;
    float* C; h16 *Ch;
    int flags;
    int start, tx;
};
struct GemmBatch { GemmDesc g[3]; int n; };

// ---------------- batched fp16 tensor-core GEMM (R12-proven) ----------------
__global__ __launch_bounds__(256,2) void mma_gemm_batched(GemmBatch gb)
{
    extern __shared__ h16 smem[];
    uint32_t sbase = (uint32_t)__cvta_generic_to_shared(smem);
    const int tid  = threadIdx.x;
    const int lane = tid & 31;
    const int wid  = tid >> 5;
    const int wm   = (wid & 3) * 32;
    const int wn   = (wid >> 2) * 64;

    int gi = 0;
    if (gb.n > 1 && (int)blockIdx.x >= gb.g[1].start) gi = 1;
    if (gb.n > 2 && (int)blockIdx.x >= gb.g[2].start) gi = 2;
    const GemmDesc d = gb.g[gi];

    const int rel = blockIdx.x - d.start;
    const int bn  = (rel % d.tx) * 128;
    const int bm  = (rel / d.tx) * 128;
    const int M = d.M, N = d.N;
    const int S1 = d.K1 >> 5, S2 = d.K2 >> 5, S = S1 + S2;

    float acc[2][8][4];
#pragma unroll
    for (int i=0;i<2;i++)
#pragma unroll
        for (int j=0;j<8;j++)
#pragma unroll
            for (int k=0;k<4;k++) acc[i][j][k] = 0.f;

    auto prefetch = [&](int s){
        const h16 *A,*B; int K,k0;
        if (s < S1){ A=d.A1; B=d.B1; K=d.K1; k0=s<<5; }
        else       { A=d.A2; B=d.B2; K=d.K2; k0=(s-S1)<<5; }
        uint32_t sb = sbase + (uint32_t)((s&1)*STAGE_E*2);
        int ar = tid>>2, ac = (tid&3)*8;
#pragma unroll
        for (int i=0;i<2;i++){
            int row = bm + ar + 64*i;
            bool ok = row < M;
            int sr = ok ? row : 0;
            uint32_t dd = sb + (uint32_t)(((ar+64*i)*SA + ac)*2);
            cpa16(dd, A + (size_t)sr*K + k0 + ac, ok);
        }
        int bk = tid>>4, bc = (tid&15)*8;
#pragma unroll
        for (int i=0;i<2;i++){
            int k = bk + 16*i;
            uint32_t dd = sb + (uint32_t)((ASZ + k*SB + bc)*2);
            cpa16(dd, B + (size_t)(k0 + k)*N + bn + bc, true);
        }
        asm volatile("cp.async.commit_group;");
    };

    prefetch(0);
    for (int s=0;s<S;s++){
        if (s+1 < S){
            prefetch(s+1);
            asm volatile("cp.async.wait_group 1;");
        } else {
            asm volatile("cp.async.wait_group 0;");
        }
        __syncthreads();
        uint32_t sb = sbase + (uint32_t)((s&1)*STAGE_E*2);
#pragma unroll
        for (int kk=0;kk<2;kk++){
            const int k16 = kk*16;
            const int loff = (lane>>1)&8;
            uint32_t ah[2][4];
#pragma unroll
            for (int mf=0;mf<2;mf++){
                uint32_t a = sb + (uint32_t)((((wm + mf*16 + (lane&15))*SA) + k16 + loff)*2);
                ldsm_x4(ah[mf][0],ah[mf][1],ah[mf][2],ah[mf][3], a);
            }
#pragma unroll
            for (int nb=0;nb<4;nb++){
                uint32_t a = sb + (uint32_t)((ASZ + (k16 + (lane&15))*SB + wn + nb*16 + loff)*2);
                uint32_t bh[4];
                ldsm_x4t(bh[0],bh[1],bh[2],bh[3], a);
#pragma unroll
                for (int h=0;h<2;h++){
#pragma unroll
                    for (int mf=0;mf<2;mf++){
                        mma_f16(acc[mf][nb*2+h], ah[mf], bh[2*h], bh[2*h+1]);
                    }
                }
            }
        }
        __syncthreads();
    }

    const int fl = d.flags;
#pragma unroll
    for (int mf=0;mf<2;mf++){
#pragma unroll
        for (int nf=0;nf<8;nf++){
            int col = bn + wn + nf*8 + (lane&3)*2;
#pragma unroll
            for (int half=0;half<2;half++){
                int row = bm + wm + mf*16 + (lane>>2) + half*8;
                if (row >= M) continue;
                float v0 = acc[mf][nf][half*2+0];
                float v1 = acc[mf][nf][half*2+1];
                if (fl & F_BIAS){ v0 += __ldg(&d.bias[col]); v1 += __ldg(&d.bias[col+1]); }
                if (fl & F_GATH){
                    int g = __ldg(&d.idx[row]);
                    const float* e = d.Demb + (size_t)g*N + col;
                    v0 += __ldg(&e[0]); v1 += __ldg(&e[1]);
                }
                if (fl & F_RELU){ v0 = fmaxf(v0,0.f); v1 = fmaxf(v1,0.f); }
                if (fl & F_HALF){
                    *(h162*)(d.Ch + (size_t)row*N + col) =
                        __halves2half2(__float2half_rn(v0), __float2half_rn(v1));
                } else {
                    float2 o; o.x=v0; o.y=v1;
                    *(float2*)(d.C + (size_t)row*N + col) = o;
                }
            }
        }
    }
}

// ---------------- single merged convert fp32 -> fp16 (12 segments) ----------------
struct CvtSet { const float* x[12]; h16* h[12]; int start[13]; };
__global__ void cvt_kernel(CvtSet cs)
{
    int q = blockIdx.x*blockDim.x + threadIdx.x;
    if (q >= cs.start[12]) return;
    int z = 0;
#pragma unroll
    for (int i = 1; i < 12; i++) if (q >= cs.start[i]) z = i;
    int off = q - cs.start[z];
    float4 v = ((const float4*)cs.x[z])[off];
    h162* H = (h162*)cs.h[z];
    H[2*off]   = __halves2half2(__float2half_rn(v.x), __float2half_rn(v.y));
    H[2*off+1] = __halves2half2(__float2half_rn(v.z), __float2half_rn(v.w));
}

// ---------------- CSR build ----------------
__global__ void zero_kernel(int* a, int na, int* b, int nb)
{
    int i = blockIdx.x*blockDim.x + threadIdx.x;
    if (i < na) a[i] = 0;
    if (i < nb) b[i] = 0;
}

__global__ void count_edges_kernel(const int* __restrict__ src, const int* __restrict__ dst,
                                   int* __restrict__ cm, int* __restrict__ cd, int E)
{
    int i = blockIdx.x * blockDim.x + threadIdx.x;
    if (i < E) {
        atomicAdd(&cd[dst[i]], 1);
        atomicAdd(&cm[src[i]], 1);
    }
}

__global__ void exscan2_kernel(const int* __restrict__ cnt_d, int* __restrict__ off_d, int* __restrict__ cur_d, int n_d,
                               const int* __restrict__ cnt_m, int* __restrict__ off_m, int* __restrict__ cur_m, int n_m)
{
    const int* cnt; int* off; int* cur; int n;
    if (blockIdx.x == 0){ cnt = cnt_d; off = off_d; cur = cur_d; n = n_d; }
    else               { cnt = cnt_m; off = off_m; cur = cur_m; n = n_m; }
    __shared__ int wsum[32];
    int t = threadIdx.x;
    int chunk = (n + 1023) >> 10;
    int s = t * chunk; if (s > n) s = n;
    int e = s + chunk; if (e > n) e = n;
    int sum = 0;
    for (int i = s; i < e; i++) sum += cnt[i];
    int lane = t & 31, w = t >> 5;
    int v = sum;
#pragma unroll
    for (int dd = 1; dd < 32; dd <<= 1){
        int o = __shfl_up_sync(0xFFFFFFFFu, v, dd);
        if (lane >= dd) v += o;
    }
    if (lane == 31) wsum[w] = v;
    __syncthreads();
    if (w == 0){
        int x = wsum[lane];
#pragma unroll
        for (int dd = 1; dd < 32; dd <<= 1){
            int o = __shfl_up_sync(0xFFFFFFFFu, x, dd);
            if (lane >= dd) x += o;
        }
        wsum[lane] = x;
    }
    __syncthreads();
    int run = v - sum + (w > 0 ? wsum[w-1] : 0);
    for (int i = s; i < e; i++){
        off[i] = run; cur[i] = run; run += cnt[i];
    }
    if (t == 1023) off[n] = run;
}

__global__ void fill_csr_kernel(const int* __restrict__ src, const int* __restrict__ dst,
                                int* __restrict__ cur_m, int* __restrict__ cur_d,
                                int* __restrict__ csr_src, int* __restrict__ csr_dst, int E)
{
    int i = blockIdx.x * blockDim.x + threadIdx.x;
    if (i < E) {
        int m = src[i], d = dst[i];
        int p = atomicAdd(&cur_d[d], 1);
        csr_src[p] = m;
        int q = atomicAdd(&cur_m[m], 1);
        csr_dst[q] = d;
    }
}

// ---------------- segment mean: fp16-in -> fp16-out (2-edge unrolled) ----------------
template<int WIDTH>
__global__ void seg_mean_kernel(const h16* __restrict__ X,
                                const int* __restrict__ off, const int* __restrict__ nbr,
                                h16* __restrict__ C)
{
    int row = blockIdx.x;
    int t = threadIdx.x;
    int s = off[row], e = off[row + 1];
    float a0=0.f,a1=0.f,a2=0.f,a3=0.f;
    float b0=0.f,b1=0.f,b2=0.f,b3=0.f;
    int i = s;
    for (; i + 2 <= e; i += 2){
        int n0 = __ldg(&nbr[i]);
        int n1 = __ldg(&nbr[i+1]);
        const h162* p0 = (const h162*)(X + (size_t)n0*WIDTH);
        const h162* p1 = (const h162*)(X + (size_t)n1*WIDTH);
        float2 u0 = __half22float2(__ldg(&p0[2*t]));
        float2 u1 = __half22float2(__ldg(&p0[2*t+1]));
        float2 w0 = __half22float2(__ldg(&p1[2*t]));
        float2 w1 = __half22float2(__ldg(&p1[2*t+1]));
        a0 += u0.x; a1 += u0.y; a2 += u1.x; a3 += u1.y;
        b0 += w0.x; b1 += w0.y; b2 += w1.x; b3 += w1.y;
    }
    if (i < e){
        int n0 = __ldg(&nbr[i]);
        const h162* p0 = (const h162*)(X + (size_t)n0*WIDTH);
        float2 u0 = __half22float2(__ldg(&p0[2*t]));
        float2 u1 = __half22float2(__ldg(&p0[2*t+1]));
        a0 += u0.x; a1 += u0.y; a2 += u1.x; a3 += u1.y;
    }
    a0 += b0; a1 += b1; a2 += b2; a3 += b3;
    float inv = (e > s) ? 1.0f/(float)(e - s) : 0.0f;
    a0 *= inv; a1 *= inv; a2 *= inv; a3 *= inv;
    h162* oc = (h162*)(C + (size_t)row*WIDTH);
    oc[2*t]   = __halves2half2(__float2half_rn(a0), __float2half_rn(a1));
    oc[2*t+1] = __halves2half2(__float2half_rn(a2), __float2half_rn(a3));
}

// ---------------- seg mean (fp16 msgs) + f32 base + relu -> fp16 out ----------------
template<int WIDTH>
__global__ void seg_relu_kernel(const h16* __restrict__ Q, const float* __restrict__ Base,
                                const int* __restrict__ off, const int* __restrict__ nbr,
                                h16* __restrict__ C)
{
    int row = blockIdx.x;
    int t = threadIdx.x;
    int s = off[row], e = off[row + 1];
    float a0=0.f,a1=0.f,a2=0.f,a3=0.f;
    float b0=0.f,b1=0.f,b2=0.f,b3=0.f;
    int i = s;
    for (; i + 2 <= e; i += 2){
        int n0 = __ldg(&nbr[i]);
        int n1 = __ldg(&nbr[i+1]);
        const h162* p0 = (const h162*)(Q + (size_t)n0*WIDTH);
        const h162* p1 = (const h162*)(Q + (size_t)n1*WIDTH);
        float2 u0 = __half22float2(__ldg(&p0[2*t]));
        float2 u1 = __half22float2(__ldg(&p0[2*t+1]));
        float2 w0 = __half22float2(__ldg(&p1[2*t]));
        float2 w1 = __half22float2(__ldg(&p1[2*t+1]));
        a0 += u0.x; a1 += u0.y; a2 += u1.x; a3 += u1.y;
        b0 += w0.x; b1 += w0.y; b2 += w1.x; b3 += w1.y;
    }
    if (i < e){
        int n0 = __ldg(&nbr[i]);
        const h162* p0 = (const h162*)(Q + (size_t)n0*WIDTH);
        float2 u0 = __half22float2(__ldg(&p0[2*t]));
        float2 u1 = __half22float2(__ldg(&p0[2*t+1]));
        a0 += u0.x; a1 += u0.y; a2 += u1.x; a3 += u1.y;
    }
    a0 += b0; a1 += b1; a2 += b2; a3 += b3;
    float inv = (e > s) ? 1.0f/(float)(e - s) : 0.0f;
    float4 bb = __ldg((const float4*)(Base + (size_t)row*WIDTH) + t);
    float x0 = fmaxf(bb.x + a0*inv, 0.f);
    float x1 = fmaxf(bb.y + a1*inv, 0.f);
    float x2 = fmaxf(bb.z + a2*inv, 0.f);
    float x3 = fmaxf(bb.w + a3*inv, 0.f);
    h162* oc = (h162*)(C + (size_t)row*WIDTH);
    oc[2*t]   = __halves2half2(__float2half_rn(x0), __float2half_rn(x1));
    oc[2*t+1] = __halves2half2(__float2half_rn(x2), __float2half_rn(x3));
}

// ---------------- seg mean: fp16-in, accumulate into f32 out ----------------
template <int WIDTH>
__global__ void seg_mean_acc_kernel(const h16* __restrict__ X, const int* __restrict__ off,
                                    const int* __restrict__ nbr, float* __restrict__ C)
{
    int row = blockIdx.x;
    int t = threadIdx.x;
    int s = off[row], e = off[row + 1];
    float a0=0.f,a1=0.f,a2=0.f,a3=0.f;
    float b0=0.f,b1=0.f,b2=0.f,b3=0.f;
    int i = s;
    for (; i + 2 <= e; i += 2){
        int n0 = __ldg(&nbr[i]);
        int n1 = __ldg(&nbr[i+1]);
        const h162* p0 = (const h162*)(X + (size_t)n0*WIDTH);
        const h162* p1 = (const h162*)(X + (size_t)n1*WIDTH);
        float2 u0 = __half22float2(__ldg(&p0[2*t]));
        float2 u1 = __half22float2(__ldg(&p0[2*t+1]));
        float2 w0 = __half22float2(__ldg(&p1[2*t]));
        float2 w1 = __half22float2(__ldg(&p1[2*t+1]));
        a0 += u0.x; a1 += u0.y; a2 += u1.x; a3 += u1.y;
        b0 += w0.x; b1 += w0.y; b2 += w1.x; b3 += w1.y;
    }
    if (i < e){
        int n0 = __ldg(&nbr[i]);
        const h162* p0 = (const h162*)(X + (size_t)n0*WIDTH);
        float2 u0 = __half22float2(__ldg(&p0[2*t]));
        float2 u1 = __half22float2(__ldg(&p0[2*t+1]));
        a0 += u0.x; a1 += u0.y; a2 += u1.x; a3 += u1.y;
    }
    a0 += b0; a1 += b1; a2 += b2; a3 += b3;
    float inv = (e > s) ? 1.0f / (float)(e - s) : 0.0f;
    float4* cp = (float4*)(C + (size_t)row * WIDTH) + t;
    float4 o = *cp;
    o.x += a0*inv; o.y += a1*inv; o.z += a2*inv; o.w += a3*inv;
    *cp = o;
}

// ---------------- host orchestration ----------------
#define SYM(p, s) cudaGetSymbolAddress((void**)&(p), s)

static inline GemmDesc mk_desc(
    const h16* A1, const h16* B1, int K1,
    const h16* A2, const h16* B2, int K2,
    int M, int N, const float* bias, const float* Demb, const int* idx,
    float* C, h16* Ch, int flags)
{
    GemmDesc d;
    d.A1=A1; d.B1=B1; d.K1=K1;
    d.A2=A2; d.B2=B2; d.K2=K2;
    d.M=M; d.N=N; d.bias=bias; d.Demb=Demb; d.idx=idx;
    d.C=C; d.Ch=Ch; d.flags=flags;
    d.start=0; d.tx=N/128;
    return d;
}

static inline void launch_batch(GemmDesc* descs, int n, cudaStream_t st)
{
    GemmBatch gb;
    int total = 0;
    for (int i = 0; i < n; i++){
        descs[i].start = total;
        total += descs[i].tx * ((descs[i].M + 127)/128);
        gb.g[i] = descs[i];
    }
    for (int i = n; i < 3; i++){ gb.g[i] = descs[n-1]; gb.g[i].start = 0x7FFFFFFF; }
    gb.n = n;
    mma_gemm_batched<<<total, 256, GEMM_SMEM_BYTES, st>>>(gb);
}

// static aux resources (created on first, uncaptured, call)
struct Aux {
    cudaStream_t s2;
    cudaEvent_t ev[4];
    Aux(){
        cudaStreamCreateWithFlags(&s2, cudaStreamNonBlocking);
        for (int i = 0; i < 4; i++)
            cudaEventCreateWithFlags(&ev[i], cudaEventDisableTiming);
    }
};

extern "C" void kernel_launch(void* const* d_in, const int* in_sizes, int n_in,
                              void* d_out, int out_size)
{
    static Aux aux;

    cudaStream_t ms = cudaStreamPerThread;
    {
        cudaStreamCaptureStatus st = cudaStreamCaptureStatusNone;
        if (cudaStreamIsCapturing(cudaStreamPerThread, &st) == cudaSuccess &&
            st == cudaStreamCaptureStatusActive) {
            ms = cudaStreamPerThread;
        } else {
            cudaGetLastError();
            st = cudaStreamCaptureStatusNone;
            if (cudaStreamIsCapturing(cudaStreamLegacy, &st) == cudaSuccess &&
                st == cudaStreamCaptureStatusActive) {
                ms = cudaStreamLegacy;
            }
            cudaGetLastError();
        }
    }
    cudaStream_t s2 = aux.s2;

    const float* mf   = (const float*)d_in[0];
    const float* df   = (const float*)d_in[1];
    const int*   mid  = (const int*)d_in[2];
    const int*   did  = (const int*)d_in[3];
    const int*   esrc = (const int*)d_in[4];
    const int*   edst = (const int*)d_in[5];
    const float* Wm   = (const float*)d_in[6];
    const float* bm   = (const float*)d_in[7];
    const float* Wd   = (const float*)d_in[8];
    const float* bd   = (const float*)d_in[9];
    const float* memb = (const float*)d_in[10];
    const float* demb = (const float*)d_in[11];
    const float* W1mdl = (const float*)d_in[12];
    const float* b1md  = (const float*)d_in[13];
    const float* W1mdr = (const float*)d_in[14];
    const float* W1dml = (const float*)d_in[15];
    const float* b1dm  = (const float*)d_in[16];
    const float* W1dmr = (const float*)d_in[17];
    const float* W2mdl = (const float*)d_in[18];
    const float* b2md  = (const float*)d_in[19];
    const float* W2mdr = (const float*)d_in[20];
    const float* W2dml = (const float*)d_in[21];
    const float* b2dm  = (const float*)d_in[22];
    const float* W2dmr = (const float*)d_in[23];

    float* out = (float*)d_out;
    float* o_m = out;
    float* o_d = out + (size_t)NM * OD;

    h16 *mfh,*dfh,*xm,*xd,*ad,*ad2,*hm,*hd,*qd,*ud;
    h16 *wm,*wd,*w1mdl,*w1mdr,*w1dml,*w1dmr,*w2mdl,*w2mdr,*w2dml,*w2dmr;
    float *basem;
    int *cnt_m,*cnt_d,*off_m,*off_d,*cur_m,*cur_d,*csr_src,*csr_dst;
    SYM(mfh,g_mf); SYM(dfh,g_df);
    SYM(xm,g_xm); SYM(xd,g_xd);
    SYM(ad,g_ad); SYM(ad2,g_ad2);
    SYM(hm,g_hm); SYM(hd,g_hd);
    SYM(qd,g_qd); SYM(ud,g_ud);
    SYM(wm,g_wm); SYM(wd,g_wd);
    SYM(w1mdl,g_w1mdl); SYM(w1mdr,g_w1mdr); SYM(w1dml,g_w1dml); SYM(w1dmr,g_w1dmr);
    SYM(w2mdl,g_w2mdl); SYM(w2mdr,g_w2mdr); SYM(w2dml,g_w2dml); SYM(w2dmr,g_w2dmr);
    SYM(basem,g_base);
    SYM(cnt_m,g_cnt_m); SYM(cnt_d,g_cnt_d); SYM(off_m,g_off_m); SYM(off_d,g_off_d);
    SYM(cur_m,g_cur_m); SYM(cur_d,g_cur_d); SYM(csr_src,g_csr_src); SYM(csr_dst,g_csr_dst);

    cudaFuncSetAttribute(mma_gemm_batched, cudaFuncAttributeMaxDynamicSharedMemorySize, GEMM_SMEM_BYTES);

    // ---- fork s2: CSR chain overlaps with converts+encoders ----
    cudaEventRecord(aux.ev[0], ms);
    cudaStreamWaitEvent(s2, aux.ev[0], 0);
    zero_kernel<<<(NM + 255)/256, 256, 0, s2>>>(cnt_m, NM, cnt_d, ND);
    count_edges_kernel<<<(NE + 255) / 256, 256, 0, s2>>>(esrc, edst, cnt_m, cnt_d, NE);
    exscan2_kernel<<<2, 1024, 0, s2>>>(cnt_d, off_d, cur_d, ND, cnt_m, off_m, cur_m, NM);
    fill_csr_kernel<<<(NE + 255) / 256, 256, 0, s2>>>(esrc, edst, cur_m, cur_d, csr_src, csr_dst, NE);
    cudaEventRecord(aux.ev[1], s2);   // CSR ready

    // ---- main: one merged convert launch (12 segments) ----
    {
        CvtSet cs;
        const float* xs[12] = {mf, df, Wm, Wd, W1mdl, W1mdr, W1dml, W1dmr,
                               W2mdl, W2mdr, W2dml, W2dmr};
        h16* hs[12] = {mfh, dfh, wm, wd, w1mdl, w1mdr, w1dml, w1dmr,
                       w2mdl, w2mdr, w2dml, w2dmr};
        int n4s[12] = {NM*FIN/4, ND*FIN/4, FIN*HD/4, FIN*HD/4,
                       HD*H1/4, HD*H1/4, HD*H1/4, HD*H1/4,
                       H1*OD/4, H1*OD/4, H1*OD/4, H1*OD/4};
        int run = 0;
        for (int i = 0; i < 12; i++){
            cs.x[i] = xs[i]; cs.h[i] = hs[i]; cs.start[i] = run; run += n4s[i];
        }
        cs.start[12] = run;
        cvt_kernel<<<(run + 255)/256, 256, 0, ms>>>(cs);
    }

    // ---- main: L1 encoders ----
    {
        GemmDesc ds[2] = {
            mk_desc(mfh, wm, FIN, 0,0, 0,
                    NM, HD, bm, memb, mid, nullptr, xm, F_BIAS|F_GATH|F_HALF),
            mk_desc(dfh, wd, FIN, 0,0, 0,
                    ND, HD, bd, demb, did, nullptr, xd, F_BIAS|F_GATH|F_HALF)
        };
        launch_batch(ds, 2, ms);
    }

    // join: CSR must be ready before first gather
    cudaStreamWaitEvent(ms, aux.ev[1], 0);

    // ---- main: layer1 md aggregation ----
    seg_mean_kernel<HD><<<ND, HD/4, 0, ms>>>(xm, off_d, csr_src, ad);

    // ---- main: Group B: L1md-dual + qd + base_m ----
    {
        GemmDesc ds[3] = {
            mk_desc(ad, w1mdl, HD, xd, w1mdr, HD,
                    ND, H1, b1md, nullptr, nullptr, nullptr, hd, F_BIAS|F_RELU|F_HALF),
            mk_desc(xd, w1dml, HD, 0,0, 0,
                    ND, H1, nullptr, nullptr, nullptr, nullptr, qd, F_HALF),
            mk_desc(xm, w1dmr, HD, 0,0, 0,
                    NM, H1, b1dm, nullptr, nullptr, basem, nullptr, F_BIAS)
        };
        launch_batch(ds, 3, ms);
    }

    // ---- main: h_m = relu(base + mean(q_d)); layer2 md aggregation ----
    seg_relu_kernel<H1><<<NM, H1/4, 0, ms>>>(qd, basem, off_m, csr_dst, hm);
    seg_mean_kernel<H1><<<ND, H1/4, 0, ms>>>(hm, off_d, csr_src, ad2);

    // ---- main: Group C: L2md-dual + ud + o_m base ----
    {
        GemmDesc ds[3] = {
            mk_desc(ad2, w2mdl, H1, hd, w2mdr, H1,
                    ND, OD, b2md, nullptr, nullptr, o_d, nullptr, F_BIAS),
            mk_desc(hd, w2dml, H1, 0,0, 0,
                    ND, OD, nullptr, nullptr, nullptr, nullptr, ud, F_HALF),
            mk_desc(hm, w2dmr, H1, 0,0, 0,
                    NM, OD, b2dm, nullptr, nullptr, o_m, nullptr, F_BIAS)
        };
        launch_batch(ds, 3, ms);
    }

    // ---- main: o_m += mean(ud over incident diseases) ----
    seg_mean_acc_kernel<OD><<<NM, OD/4, 0, ms>>>(ud, off_m, csr_dst, o_m);
}